// round 11
// baseline (speedup 1.0000x reference)
#include <cuda_runtime.h>
#include <cuda_bf16.h>
#include <math.h>
#include <stdint.h>

#define N_ROWS 32768
#define D_DIM  256
#define K_CODES 4096
#define NTILES 4096          // (32768/128) n-tiles x (4096/256) k-tiles
#define EPS_TIE 5e-4f

// ---- output layout (floats) ----
#define OFF_LOSS  0ull
#define OFF_QST   1ull
#define OFF_PROBS (1ull + (unsigned long long)N_ROWS * D_DIM)
#define OFF_PERP  (OFF_PROBS + (unsigned long long)N_ROWS * K_CODES)
#define OFF_IDX   (OFF_PERP + 1ull)
#define OFF_ACT   (OFF_IDX + N_ROWS)
#define OFF_USE   (OFF_ACT + 1ull)

// ---- scratch (static __device__: allocation-free) ----
static __device__ __align__(16) float g_xt[N_ROWS * D_DIM];   // tf32-rounded
static __device__ __align__(16) float g_wt[K_CODES * D_DIM];  // tf32-rounded
static __device__ __align__(16) float g_wn[K_CODES * D_DIM];  // exact fp32
static __device__ __align__(16) float g_xn[N_ROWS * D_DIM];   // exact fp32
static __device__ float g_rowsum[N_ROWS];
static __device__ unsigned long long g_cand[(size_t)N_ROWS * 32]; // per (row, kTile) min2
static __device__ float g_counts[K_CODES];
static __device__ float g_loss;

// --------------------------------------------------------------------------
__device__ __forceinline__ uint32_t smem_u32(const void* p) {
    uint32_t a;
    asm("{ .reg .u64 t; cvta.to.shared.u64 t, %1; cvt.u32.u64 %0, t; }" : "=r"(a) : "l"(p));
    return a;
}
#define CP_ASYNC16(dst, src) \
    asm volatile("cp.async.cg.shared.global [%0], [%1], 16;" :: "r"(dst), "l"(src))
#define CP_COMMIT() asm volatile("cp.async.commit_group;" ::: "memory")
#define CP_WAIT2()  asm volatile("cp.async.wait_group 2;" ::: "memory")

__device__ __forceinline__ void ldsm_x4(uint32_t* r, uint32_t addr) {
    asm volatile("ldmatrix.sync.aligned.m8n8.x4.shared.b16 {%0,%1,%2,%3}, [%4];"
                 : "=r"(r[0]), "=r"(r[1]), "=r"(r[2]), "=r"(r[3]) : "r"(addr));
}
// tf32 MMA m16n8k8, fp32 accum (baseline sm_80 PTX)
__device__ __forceinline__ void mma1688(float* d, const uint32_t* a, const uint32_t* b) {
    asm volatile("mma.sync.aligned.m16n8k8.row.col.f32.tf32.tf32.f32 "
                 "{%0,%1,%2,%3},{%4,%5,%6,%7},{%8,%9},{%0,%1,%2,%3};"
                 : "+f"(d[0]), "+f"(d[1]), "+f"(d[2]), "+f"(d[3])
                 : "r"(a[0]), "r"(a[1]), "r"(a[2]), "r"(a[3]), "r"(b[0]), "r"(b[1]));
}
// 2^t via FFMA-only poly (no MUFU). |rel err| < 2e-5.
__device__ __forceinline__ float fast_exp2(float t) {
    float fi = floorf(t);
    float f = t - fi;
    float p = 1.5403530e-4f;
    p = fmaf(p, f, 1.3333558e-3f);
    p = fmaf(p, f, 9.6181291e-3f);
    p = fmaf(p, f, 5.5504109e-2f);
    p = fmaf(p, f, 2.4022651e-1f);
    p = fmaf(p, f, 6.9314718e-1f);
    p = fmaf(p, f, 1.0f);
    return __int_as_float(__float_as_int(p) + (((int)fi) << 23));
}
__device__ __forceinline__ unsigned enc_f(float x) {
    unsigned u = __float_as_uint(x);
    return (u & 0x80000000u) ? ~u : (u | 0x80000000u);
}
__device__ __forceinline__ float dec_f(unsigned e) {
    return (e & 0x80000000u) ? __uint_as_float(e & 0x7FFFFFFFu) : __uint_as_float(~e);
}
__device__ __forceinline__ void m2merge(unsigned long long& a1, unsigned long long& a2,
                                        unsigned long long b1, unsigned long long b2) {
    unsigned long long lo = a1 < b1 ? a1 : b1;
    unsigned long long hi = a1 < b1 ? b1 : a1;
    unsigned long long mn2 = a2 < b2 ? a2 : b2;
    a1 = lo;
    a2 = hi < mn2 ? hi : mn2;
}
__device__ __forceinline__ void m2insert(unsigned long long& a1, unsigned long long& a2,
                                         unsigned long long v) {
    if (v < a1) { a2 = a1; a1 = v; }
    else if (v < a2) { a2 = v; }
}

// --------------------------------------------------------------------------
__global__ void init_kernel() {
    int i = blockIdx.x * blockDim.x + threadIdx.x;
    if (i < N_ROWS) g_rowsum[i] = 0.0f;
    if (i < K_CODES) g_counts[i] = 0.0f;
    if (i == 0) g_loss = 0.0f;
}

// --------------------------------------------------------------------------
__device__ __forceinline__ uint4 to_tf32x4(float4 v) {
    uint4 t;
    asm("cvt.rna.tf32.f32 %0, %1;" : "=r"(t.x) : "f"(v.x));
    asm("cvt.rna.tf32.f32 %0, %1;" : "=r"(t.y) : "f"(v.y));
    asm("cvt.rna.tf32.f32 %0, %1;" : "=r"(t.z) : "f"(v.z));
    asm("cvt.rna.tf32.f32 %0, %1;" : "=r"(t.w) : "f"(v.w));
    return t;
}

// one warp per row: l2-normalize; store exact fp32 + tf32-rounded copies
__global__ void normsplit_kernel(const float* __restrict__ src, int rows, int which) {
    int warp = (blockIdx.x * blockDim.x + threadIdx.x) >> 5;
    int lane = threadIdx.x & 31;
    if (warp >= rows) return;
    const float4* s4 = reinterpret_cast<const float4*>(src + (size_t)warp * D_DIM);
    float4 a = s4[lane];
    float4 b = s4[lane + 32];
    float ss = a.x*a.x + a.y*a.y + a.z*a.z + a.w*a.w
             + b.x*b.x + b.y*b.y + b.z*b.z + b.w*b.w;
    #pragma unroll
    for (int o = 16; o; o >>= 1) ss += __shfl_xor_sync(0xffffffffu, ss, o);
    float sc = 1.0f / fmaxf(sqrtf(ss), 1e-12f);
    a.x *= sc; a.y *= sc; a.z *= sc; a.w *= sc;
    b.x *= sc; b.y *= sc; b.z *= sc; b.w *= sc;
    float* dt = which ? g_xt : g_wt;
    uint4* t4 = reinterpret_cast<uint4*>(dt + (size_t)warp * D_DIM);
    t4[lane] = to_tf32x4(a);
    t4[lane + 32] = to_tf32x4(b);
    float4* d4 = reinterpret_cast<float4*>((which ? g_xn : g_wn) + (size_t)warp * D_DIM);
    d4[lane] = a;
    d4[lane + 32] = b;
}

// --------------------------------------------------------------------------
// Persistent tf32 mma.sync GEMM, fat warp tiles to cut LDSM traffic.
// CTA tile 128(n) x 256(k); 256 threads, 8 warps (2 wr x 4 wc), warp 64x64.
// BK=32 (4 ksteps of 8). 3-stage cp.async ring, continuous producer.
// smem tile: row-major 128B/row, 16B slot s stored at s ^ (row & 7).
#define STAGE_SZ  49152          // A 16KB (128 rows) + B 32KB (256 rows)
#define TILE_Aofs 0
#define TILE_Bofs 16384
#define RED_OFF   (3 * STAGE_SZ)
#define GEMM_SMEM (3 * STAGE_SZ + 10240 + 1024)
#define TWO_LOG2E 2.8853900817779268f

struct FragT {
    uint32_t a[4][4];   // [mt m16][4 regs]
    uint32_t b[4][4];   // [pair of n8][4 regs]: regs 0,1 = nt even; 2,3 = nt odd
};

__device__ __forceinline__ void load_frags_t(FragT& f, uint32_t st, int ks,
                                             int wr, int wc, int lane) {
    const int r8 = lane & 7;
    #pragma unroll
    for (int mt = 0; mt < 4; mt++) {
        int row = wr * 64 + mt * 16 + r8 + ((lane >> 3) & 1) * 8;
        int slot = ks * 2 + (lane >> 4);
        ldsm_x4(f.a[mt], st + TILE_Aofs + row * 128 + ((slot ^ (row & 7)) << 4));
    }
    #pragma unroll
    for (int pr = 0; pr < 4; pr++) {
        int row = wc * 64 + pr * 16 + r8 + (lane >> 4) * 8;
        int slot = ks * 2 + ((lane >> 3) & 1);
        ldsm_x4(f.b[pr], st + TILE_Bofs + row * 128 + ((slot ^ (row & 7)) << 4));
    }
}

__device__ __forceinline__ void mma_all_t(float (&acc)[4][8][4], const FragT& f) {
    #pragma unroll
    for (int mt = 0; mt < 4; mt++)
        #pragma unroll
        for (int nt = 0; nt < 8; nt++)
            mma1688(acc[mt][nt], f.a[mt], &f.b[nt >> 1][(nt & 1) * 2]);
}

// producer: copy BK=32 chunk pc of tile pt into stage st
__device__ __forceinline__ void produce_chunk(uint32_t st, int pt, int pc, int tid) {
    if (pt < NTILES) {
        int nB = (pt >> 4) * 128, kB = (pt & 15) * 256;
        #pragma unroll
        for (int rep = 0; rep < 4; rep++) {      // A: 128 rows x 8 slots = 1024
            int idx = tid + rep * 256;
            int row = idx >> 3, slot = idx & 7;
            uint32_t doff = (uint32_t)(row * 128 + ((slot ^ (row & 7)) << 4));
            CP_ASYNC16(st + TILE_Aofs + doff,
                       g_xt + (size_t)(nB + row) * D_DIM + pc * 32 + slot * 4);
        }
        #pragma unroll
        for (int rep = 0; rep < 8; rep++) {      // B: 256 rows x 8 slots = 2048
            int idx = tid + rep * 256;
            int row = idx >> 3, slot = idx & 7;
            uint32_t doff = (uint32_t)(row * 128 + ((slot ^ (row & 7)) << 4));
            CP_ASYNC16(st + TILE_Bofs + doff,
                       g_wt + (size_t)(kB + row) * D_DIM + pc * 32 + slot * 4);
        }
    }
    CP_COMMIT();
}

__global__ __launch_bounds__(256, 1) void gemm_kernel(float* __restrict__ out) {
    extern __shared__ char smraw[];
    uint32_t sb = (smem_u32(smraw) + 1023u) & ~1023u;
    char* smem = smraw + (sb - smem_u32(smraw));

    const int tid = threadIdx.x;
    const int wid = tid >> 5;
    const int lane = tid & 31;
    const int wr = wid >> 2;     // 0..1
    const int wc = wid & 3;      // 0..3
    const int stride = gridDim.x;

    float acc[4][8][4];
    #pragma unroll
    for (int mt = 0; mt < 4; mt++)
        #pragma unroll
        for (int nt = 0; nt < 8; nt++)
            #pragma unroll
            for (int e = 0; e < 4; e++) acc[mt][nt][e] = 0.0f;

    FragT fr;

    // producer state: 3 stages in flight
    int pt = blockIdx.x, pc = 0;
    #pragma unroll
    for (int s = 0; s < 3; s++) {
        produce_chunk(sb + s * STAGE_SZ, pt, pc, tid);
        if (++pc == 8) { pc = 0; pt += stride; }
    }

    int gphase = 0;
    float* probs = out + OFF_PROBS;
    const int qrow = lane >> 2;
    const int qcol = lane & 3;
    float* ssum = reinterpret_cast<float*>(smem + RED_OFF);                         // [4][128]
    unsigned long long* smin = reinterpret_cast<unsigned long long*>(smem + RED_OFF + 2048); // [4][128][2]

    for (int t = blockIdx.x; t < NTILES; t += stride) {
        const int nBase = (t >> 4) * 128;
        const int kBase = (t & 15) * 256;

        for (int c = 0; c < 8; c++) {
            uint32_t st = sb + gphase * STAGE_SZ;
            CP_WAIT2();
            __syncthreads();
            #pragma unroll
            for (int ks = 0; ks < 4; ks++) {
                load_frags_t(fr, st, ks, wr, wc, lane);
                mma_all_t(acc, fr);
            }
            __syncthreads();
            produce_chunk(st, pt, pc, tid);
            if (++pc == 8) { pc = 0; pt += stride; }
            gphase = (gphase + 1 == 3) ? 0 : gphase + 1;
        }

        // ---- epilogue: probs, rowsum, per-CTA min2 candidates ----
        #pragma unroll
        for (int mt = 0; mt < 4; mt++) {
            #pragma unroll
            for (int hh = 0; hh < 2; hh++) {
                int rl = wr * 64 + mt * 16 + hh * 8 + qrow;
                size_t rowOff = (size_t)(nBase + rl) * K_CODES + kBase + wc * 64;
                float s = 0.0f;
                unsigned long long b1 = 0xFFFFFFFFFFFFFFFFull, b2 = 0xFFFFFFFFFFFFFFFFull;
                #pragma unroll
                for (int nt = 0; nt < 8; nt++) {
                    float v0 = acc[mt][nt][hh * 2 + 0];
                    float v1 = acc[mt][nt][hh * 2 + 1];
                    int k0 = nt * 8 + qcol * 2;
                    float d0 = fmaf(-2.0f, v0, 2.0f);
                    float d1 = fmaf(-2.0f, v1, 2.0f);
                    float e0 = fast_exp2(v0 * TWO_LOG2E);
                    float e1 = fast_exp2(v1 * TWO_LOG2E);
                    probs[rowOff + k0] = e0;
                    probs[rowOff + k0 + 1] = e1;
                    s += e0 + e1;
                    m2insert(b1, b2, (((unsigned long long)enc_f(d0)) << 32) |
                                     (unsigned)(kBase + wc * 64 + k0));
                    m2insert(b1, b2, (((unsigned long long)enc_f(d1)) << 32) |
                                     (unsigned)(kBase + wc * 64 + k0 + 1));
                }
                s += __shfl_xor_sync(0xffffffffu, s, 1);
                s += __shfl_xor_sync(0xffffffffu, s, 2);
                #pragma unroll
                for (int o = 1; o <= 2; o <<= 1) {
                    unsigned long long o1 = __shfl_xor_sync(0xffffffffu, b1, o);
                    unsigned long long o2 = __shfl_xor_sync(0xffffffffu, b2, o);
                    m2merge(b1, b2, o1, o2);
                }
                if (qcol == 0) {
                    ssum[wc * 128 + rl] = s;
                    smin[(wc * 128 + rl) * 2 + 0] = b1;
                    smin[(wc * 128 + rl) * 2 + 1] = b2;
                }
            }
        }
        __syncthreads();
        if (tid < 128) {
            float s = 0.0f;
            unsigned long long b1 = 0xFFFFFFFFFFFFFFFFull, b2 = 0xFFFFFFFFFFFFFFFFull;
            #pragma unroll
            for (int w = 0; w < 4; w++) {
                s += ssum[w * 128 + tid];
                m2merge(b1, b2, smin[(w * 128 + tid) * 2 + 0], smin[(w * 128 + tid) * 2 + 1]);
            }
            atomicAdd(&g_rowsum[nBase + tid], s);
            size_t cb = (size_t)(nBase + tid) * 32 + (kBase >> 8) * 2;
            g_cand[cb + 0] = b1;
            g_cand[cb + 1] = b2;
        }
        // reset acc for next tile
        #pragma unroll
        for (int mt = 0; mt < 4; mt++)
            #pragma unroll
            for (int nt = 0; nt < 8; nt++)
                #pragma unroll
                for (int e = 0; e < 4; e++) acc[mt][nt][e] = 0.0f;
    }
}

// --------------------------------------------------------------------------
// one warp per row: global min2 over 32 candidates; on near-tie, recompute
// candidate distances with a SEQUENTIAL fp32 fmaf chain over d ascending.
__global__ void finalize_kernel(float* __restrict__ out) {
    __shared__ float blockLoss;
    __shared__ int candList[8][32];
    __shared__ int candCnt[8];
    int lane = threadIdx.x & 31;
    int wid = threadIdx.x >> 5;
    if (threadIdx.x == 0) blockLoss = 0.0f;
    if (lane == 0) candCnt[wid] = 0;
    __syncthreads();
    int n = blockIdx.x * 8 + wid;

    const unsigned long long* cand = &g_cand[(size_t)n * 32];
    unsigned long long b1 = cand[lane];                 // one entry per lane
    unsigned long long b2 = 0xFFFFFFFFFFFFFFFFull;
    #pragma unroll
    for (int o = 16; o; o >>= 1) {
        unsigned long long o1 = __shfl_xor_sync(0xffffffffu, b1, o);
        unsigned long long o2 = __shfl_xor_sync(0xffffffffu, b2, o);
        m2merge(b1, b2, o1, o2);
    }
    float d1 = dec_f((unsigned)(b1 >> 32));
    float d2 = dec_f((unsigned)(b2 >> 32));
    int idx = (int)(unsigned)(b1 & 0xFFFFFFFFull);
    float dmin = d1;

    if (d2 - d1 < EPS_TIE) {
        unsigned long long e0 = cand[lane];
        float de0 = dec_f((unsigned)(e0 >> 32));
        if (de0 - d1 < EPS_TIE) {
            int p = atomicAdd(&candCnt[wid], 1);
            if (p < 32) candList[wid][p] = (int)(unsigned)(e0 & 0xFFFFFFFFull);
        }
        __syncwarp();
        int cnt = candCnt[wid];
        cnt = cnt > 32 ? 32 : cnt;
        unsigned long long mine = 0xFFFFFFFFFFFFFFFFull;
        if (lane < cnt) {
            int k = candList[wid][lane];
            const float* xr = &g_xn[(size_t)n * D_DIM];
            const float* wr = &g_wn[(size_t)k * D_DIM];
            float s = 0.0f;
            #pragma unroll 8
            for (int d = 0; d < D_DIM; d++)
                s = fmaf(xr[d], wr[d], s);
            float dist = 2.0f - 2.0f * s;
            mine = (((unsigned long long)enc_f(dist)) << 32) | (unsigned)k;
        }
        #pragma unroll
        for (int o = 16; o; o >>= 1) {
            unsigned long long v = __shfl_xor_sync(0xffffffffu, mine, o);
            mine = v < mine ? v : mine;
        }
        idx = (int)(unsigned)(mine & 0xFFFFFFFFull);
        dmin = dec_f((unsigned)(mine >> 32));
    }

    if (lane == 0) {
        out[OFF_IDX + n] = (float)idx;
        atomicAdd(&g_counts[idx], 1.0f);
        g_rowsum[n] = 1.0f / g_rowsum[n];
        atomicAdd(&blockLoss, dmin);
    }
    const float* src = &g_wn[(size_t)idx * D_DIM];
    float* dst = &out[OFF_QST + (size_t)n * D_DIM];
    #pragma unroll
    for (int u = 0; u < 8; u++) dst[lane + u * 32] = src[lane + u * 32];
    __syncthreads();
    if (threadIdx.x == 0) atomicAdd(&g_loss, blockLoss);
}

// --------------------------------------------------------------------------
__global__ void scale_kernel(float* __restrict__ out) {
    float* probs = out + OFF_PROBS;
    const size_t total = (size_t)N_ROWS * K_CODES;
    size_t gtid = (size_t)blockIdx.x * blockDim.x + threadIdx.x;
    if (gtid < 3) probs[gtid] *= g_rowsum[0];
    if (gtid == 3) probs[total - 1] *= g_rowsum[N_ROWS - 1];

    float4* p4 = reinterpret_cast<float4*>(probs + 3);
    const size_t total4 = (total - 3) / 4;
    const size_t stride = (size_t)gridDim.x * blockDim.x;
    for (size_t i = gtid; i < total4; i += stride) {
        size_t base = 3 + i * 4;
        float i0 = g_rowsum[(base + 0) >> 12];
        float i1 = g_rowsum[(base + 1) >> 12];
        float i2 = g_rowsum[(base + 2) >> 12];
        float i3 = g_rowsum[(base + 3) >> 12];
        float4 v = p4[i];
        v.x *= i0; v.y *= i1; v.z *= i2; v.w *= i3;
        p4[i] = v;
    }
}

// --------------------------------------------------------------------------
__global__ void scalars_kernel(float* __restrict__ out) {
    __shared__ float sEnt[256];
    __shared__ int sAct[256];
    int tid = threadIdx.x;
    float ent = 0.0f;
    int act = 0;
    for (int k = tid; k < K_CODES; k += 256) {
        float c = g_counts[k];
        float p = c * (1.0f / (float)N_ROWS);
        ent += p * logf(p + 1e-10f);
        act += (c > 0.0f) ? 1 : 0;
    }
    sEnt[tid] = ent;
    sAct[tid] = act;
    __syncthreads();
    for (int s = 128; s; s >>= 1) {
        if (tid < s) { sEnt[tid] += sEnt[tid + s]; sAct[tid] += sAct[tid + s]; }
        __syncthreads();
    }
    if (tid == 0) {
        out[OFF_LOSS] = 0.25f * g_loss / (float)((size_t)N_ROWS * D_DIM);
        out[OFF_PERP] = expf(-sEnt[0]);
        out[OFF_ACT]  = (float)sAct[0];
        out[OFF_USE]  = (float)sAct[0] * (100.0f / (float)K_CODES);
    }
}

// --------------------------------------------------------------------------
extern "C" void kernel_launch(void* const* d_in, const int* in_sizes, int n_in,
                              void* d_out, int out_size) {
    const float* inp = (const float*)d_in[0];   // (16,2048,256) fp32
    const float* w   = (const float*)d_in[1];   // (4096,256) fp32
    float* out = (float*)d_out;

    int dev = 0, sms = 148;
    cudaGetDevice(&dev);
    cudaDeviceGetAttribute(&sms, cudaDevAttrMultiProcessorCount, dev);
    if (sms <= 0 || sms > NTILES) sms = 148;

    cudaFuncSetAttribute(gemm_kernel, cudaFuncAttributeMaxDynamicSharedMemorySize, GEMM_SMEM);

    init_kernel<<<128, 256>>>();
    normsplit_kernel<<<K_CODES / 8, 256>>>(w, K_CODES, 0);
    normsplit_kernel<<<N_ROWS / 8, 256>>>(inp, N_ROWS, 1);
    gemm_kernel<<<sms, 256, GEMM_SMEM>>>(out);
    finalize_kernel<<<N_ROWS / 8, 256>>>(out);
    scale_kernel<<<4096, 256>>>(out);
    scalars_kernel<<<1, 256>>>(out);
}

// round 12
// speedup vs baseline: 1.1263x; 1.1263x over previous
#include <cuda_runtime.h>
#include <cuda_bf16.h>
#include <math.h>
#include <stdint.h>

#define N_ROWS 32768
#define D_DIM  256
#define K_CODES 4096
#define NTILES 4096          // 256 n-tiles x 16 k-tiles
#define EPS_TIE 5e-4f

// ---- output layout (floats) ----
#define OFF_LOSS  0ull
#define OFF_QST   1ull
#define OFF_PROBS (1ull + (unsigned long long)N_ROWS * D_DIM)
#define OFF_PERP  (OFF_PROBS + (unsigned long long)N_ROWS * K_CODES)
#define OFF_IDX   (OFF_PERP + 1ull)
#define OFF_ACT   (OFF_IDX + N_ROWS)
#define OFF_USE   (OFF_ACT + 1ull)

// ---- scratch (static __device__: allocation-free) ----
static __device__ __align__(16) float g_xt[N_ROWS * D_DIM];   // tf32-rounded
static __device__ __align__(16) float g_wt[K_CODES * D_DIM];  // tf32-rounded
static __device__ __align__(16) float g_wn[K_CODES * D_DIM];  // exact fp32
static __device__ __align__(16) float g_xn[N_ROWS * D_DIM];   // exact fp32
static __device__ float g_rowsum[N_ROWS];
static __device__ unsigned long long g_cand[(size_t)N_ROWS * 32]; // per (row, kTile) min2
static __device__ float g_counts[K_CODES];
static __device__ float g_loss;

// --------------------------------------------------------------------------
__device__ __forceinline__ uint32_t smem_u32(const void* p) {
    uint32_t a;
    asm("{ .reg .u64 t; cvta.to.shared.u64 t, %1; cvt.u32.u64 %0, t; }" : "=r"(a) : "l"(p));
    return a;
}
#define CP_ASYNC16(dst, src) \
    asm volatile("cp.async.cg.shared.global [%0], [%1], 16;" :: "r"(dst), "l"(src))
#define CP_COMMIT() asm volatile("cp.async.commit_group;" ::: "memory")
#define CP_WAIT2()  asm volatile("cp.async.wait_group 2;" ::: "memory")

__device__ __forceinline__ void ldsm_x4(uint32_t* r, uint32_t addr) {
    asm volatile("ldmatrix.sync.aligned.m8n8.x4.shared.b16 {%0,%1,%2,%3}, [%4];"
                 : "=r"(r[0]), "=r"(r[1]), "=r"(r[2]), "=r"(r[3]) : "r"(addr));
}
// tf32 MMA m16n8k8, fp32 accum (baseline sm_80 PTX)
__device__ __forceinline__ void mma1688(float* d, const uint32_t* a, const uint32_t* b) {
    asm volatile("mma.sync.aligned.m16n8k8.row.col.f32.tf32.tf32.f32 "
                 "{%0,%1,%2,%3},{%4,%5,%6,%7},{%8,%9},{%0,%1,%2,%3};"
                 : "+f"(d[0]), "+f"(d[1]), "+f"(d[2]), "+f"(d[3])
                 : "r"(a[0]), "r"(a[1]), "r"(a[2]), "r"(a[3]), "r"(b[0]), "r"(b[1]));
}
// 2^t via FFMA-only poly (no MUFU). |rel err| < 2e-5.
__device__ __forceinline__ float fast_exp2(float t) {
    float fi = floorf(t);
    float f = t - fi;
    float p = 1.5403530e-4f;
    p = fmaf(p, f, 1.3333558e-3f);
    p = fmaf(p, f, 9.6181291e-3f);
    p = fmaf(p, f, 5.5504109e-2f);
    p = fmaf(p, f, 2.4022651e-1f);
    p = fmaf(p, f, 6.9314718e-1f);
    p = fmaf(p, f, 1.0f);
    return __int_as_float(__float_as_int(p) + (((int)fi) << 23));
}
__device__ __forceinline__ unsigned enc_f(float x) {
    unsigned u = __float_as_uint(x);
    return (u & 0x80000000u) ? ~u : (u | 0x80000000u);
}
__device__ __forceinline__ float dec_f(unsigned e) {
    return (e & 0x80000000u) ? __uint_as_float(e & 0x7FFFFFFFu) : __uint_as_float(~e);
}
__device__ __forceinline__ void m2merge(unsigned long long& a1, unsigned long long& a2,
                                        unsigned long long b1, unsigned long long b2) {
    unsigned long long lo = a1 < b1 ? a1 : b1;
    unsigned long long hi = a1 < b1 ? b1 : a1;
    unsigned long long mn2 = a2 < b2 ? a2 : b2;
    a1 = lo;
    a2 = hi < mn2 ? hi : mn2;
}
__device__ __forceinline__ void m2insert(unsigned long long& a1, unsigned long long& a2,
                                         unsigned long long v) {
    if (v < a1) { a2 = a1; a1 = v; }
    else if (v < a2) { a2 = v; }
}

// --------------------------------------------------------------------------
__global__ void init_kernel() {
    int i = blockIdx.x * blockDim.x + threadIdx.x;
    if (i < N_ROWS) g_rowsum[i] = 0.0f;
    if (i < K_CODES) g_counts[i] = 0.0f;
    if (i == 0) g_loss = 0.0f;
}

// --------------------------------------------------------------------------
__device__ __forceinline__ uint4 to_tf32x4(float4 v) {
    uint4 t;
    asm("cvt.rna.tf32.f32 %0, %1;" : "=r"(t.x) : "f"(v.x));
    asm("cvt.rna.tf32.f32 %0, %1;" : "=r"(t.y) : "f"(v.y));
    asm("cvt.rna.tf32.f32 %0, %1;" : "=r"(t.z) : "f"(v.z));
    asm("cvt.rna.tf32.f32 %0, %1;" : "=r"(t.w) : "f"(v.w));
    return t;
}

// one warp per row: l2-normalize; store exact fp32 + tf32-rounded copies
__global__ void normsplit_kernel(const float* __restrict__ src, int rows, int which) {
    int warp = (blockIdx.x * blockDim.x + threadIdx.x) >> 5;
    int lane = threadIdx.x & 31;
    if (warp >= rows) return;
    const float4* s4 = reinterpret_cast<const float4*>(src + (size_t)warp * D_DIM);
    float4 a = s4[lane];
    float4 b = s4[lane + 32];
    float ss = a.x*a.x + a.y*a.y + a.z*a.z + a.w*a.w
             + b.x*b.x + b.y*b.y + b.z*b.z + b.w*b.w;
    #pragma unroll
    for (int o = 16; o; o >>= 1) ss += __shfl_xor_sync(0xffffffffu, ss, o);
    float sc = 1.0f / fmaxf(sqrtf(ss), 1e-12f);
    a.x *= sc; a.y *= sc; a.z *= sc; a.w *= sc;
    b.x *= sc; b.y *= sc; b.z *= sc; b.w *= sc;
    float* dt = which ? g_xt : g_wt;
    uint4* t4 = reinterpret_cast<uint4*>(dt + (size_t)warp * D_DIM);
    t4[lane] = to_tf32x4(a);
    t4[lane + 32] = to_tf32x4(b);
    float4* d4 = reinterpret_cast<float4*>((which ? g_xn : g_wn) + (size_t)warp * D_DIM);
    d4[lane] = a;
    d4[lane + 32] = b;
}

// --------------------------------------------------------------------------
// Persistent tf32 mma.sync GEMM.
// CTA tile 128(n) x 256(k); 512 threads, 16 warps (4 wr x 4 wc), warp 32x64.
// BK=32 (4 ksteps of 8). 3-stage cp.async ring, continuous producer.
// smem tile: row-major 128B/row, 16B slot s stored at s ^ (row & 7).
#define STAGE_SZ  49152          // A 16KB (128 rows) + B 32KB (256 rows)
#define TILE_Aofs 0
#define TILE_Bofs 16384
#define RED_OFF   (3 * STAGE_SZ)
#define GEMM_SMEM (3 * STAGE_SZ + 10240 + 1024)
#define TWO_LOG2E 2.8853900817779268f

struct FragT {
    uint32_t a[2][4];   // [mt m16][4 regs]
    uint32_t b[4][4];   // [pair of n8][4 regs]: regs 0,1 = nt even; 2,3 = nt odd
};

__device__ __forceinline__ void load_frags_t(FragT& f, uint32_t st, int ks,
                                             int wr, int wc, int lane) {
    const int r8 = lane & 7;
    #pragma unroll
    for (int mt = 0; mt < 2; mt++) {
        int row = wr * 32 + mt * 16 + r8 + ((lane >> 3) & 1) * 8;
        int slot = ks * 2 + (lane >> 4);
        ldsm_x4(f.a[mt], st + TILE_Aofs + row * 128 + ((slot ^ (row & 7)) << 4));
    }
    #pragma unroll
    for (int pr = 0; pr < 4; pr++) {
        int row = wc * 64 + pr * 16 + r8 + (lane >> 4) * 8;
        int slot = ks * 2 + ((lane >> 3) & 1);
        ldsm_x4(f.b[pr], st + TILE_Bofs + row * 128 + ((slot ^ (row & 7)) << 4));
    }
}

__device__ __forceinline__ void mma_all_t(float (&acc)[2][8][4], const FragT& f) {
    #pragma unroll
    for (int mt = 0; mt < 2; mt++)
        #pragma unroll
        for (int nt = 0; nt < 8; nt++)
            mma1688(acc[mt][nt], f.a[mt], &f.b[nt >> 1][(nt & 1) * 2]);
}

// producer: copy BK=32 chunk pc of tile pt into stage st
__device__ __forceinline__ void produce_chunk(uint32_t st, int pt, int pc, int tid) {
    if (pt < NTILES) {
        int nB = (pt >> 4) * 128, kB = (pt & 15) * 256;
        #pragma unroll
        for (int rep = 0; rep < 2; rep++) {      // A: 128 rows x 8 slots = 1024
            int idx = tid + rep * 512;
            int row = idx >> 3, slot = idx & 7;
            uint32_t doff = (uint32_t)(row * 128 + ((slot ^ (row & 7)) << 4));
            CP_ASYNC16(st + TILE_Aofs + doff,
                       g_xt + (size_t)(nB + row) * D_DIM + pc * 32 + slot * 4);
        }
        #pragma unroll
        for (int rep = 0; rep < 4; rep++) {      // B: 256 rows x 8 slots = 2048
            int idx = tid + rep * 512;
            int row = idx >> 3, slot = idx & 7;
            uint32_t doff = (uint32_t)(row * 128 + ((slot ^ (row & 7)) << 4));
            CP_ASYNC16(st + TILE_Bofs + doff,
                       g_wt + (size_t)(kB + row) * D_DIM + pc * 32 + slot * 4);
        }
    }
    CP_COMMIT();
}

__global__ __launch_bounds__(512, 1) void gemm_kernel(float* __restrict__ out) {
    extern __shared__ char smraw[];
    uint32_t sb = (smem_u32(smraw) + 1023u) & ~1023u;
    char* smem = smraw + (sb - smem_u32(smraw));

    const int tid = threadIdx.x;
    const int wid = tid >> 5;
    const int lane = tid & 31;
    const int wr = wid >> 2;     // 0..3 -> 32 n-rows each
    const int wc = wid & 3;      // 0..3 -> 64 k-cols each
    const int stride = gridDim.x;

    float acc[2][8][4];
    #pragma unroll
    for (int mt = 0; mt < 2; mt++)
        #pragma unroll
        for (int nt = 0; nt < 8; nt++)
            #pragma unroll
            for (int e = 0; e < 4; e++) acc[mt][nt][e] = 0.0f;

    FragT fr;

    // producer state: 3 stages in flight
    int pt = blockIdx.x, pc = 0;
    #pragma unroll
    for (int s = 0; s < 3; s++) {
        produce_chunk(sb + s * STAGE_SZ, pt, pc, tid);
        if (++pc == 8) { pc = 0; pt += stride; }
    }

    int gphase = 0;
    float* probs = out + OFF_PROBS;
    const int qrow = lane >> 2;
    const int qcol = lane & 3;
    float* ssum = reinterpret_cast<float*>(smem + RED_OFF);                         // [4][128]
    unsigned long long* smin = reinterpret_cast<unsigned long long*>(smem + RED_OFF + 2048); // [4][128][2]

    for (int t = blockIdx.x; t < NTILES; t += stride) {
        const int nBase = (t >> 4) * 128;
        const int kBase = (t & 15) * 256;

        for (int c = 0; c < 8; c++) {
            uint32_t st = sb + gphase * STAGE_SZ;
            CP_WAIT2();
            __syncthreads();
            #pragma unroll
            for (int ks = 0; ks < 4; ks++) {
                load_frags_t(fr, st, ks, wr, wc, lane);
                mma_all_t(acc, fr);
            }
            __syncthreads();
            produce_chunk(st, pt, pc, tid);
            if (++pc == 8) { pc = 0; pt += stride; }
            gphase = (gphase + 1 == 3) ? 0 : gphase + 1;
        }

        // ---- epilogue: probs, rowsum, per-CTA min2 candidates ----
        #pragma unroll
        for (int mt = 0; mt < 2; mt++) {
            #pragma unroll
            for (int hh = 0; hh < 2; hh++) {
                int rl = wr * 32 + mt * 16 + hh * 8 + qrow;
                size_t rowOff = (size_t)(nBase + rl) * K_CODES + kBase + wc * 64;
                float s = 0.0f;
                unsigned long long b1 = 0xFFFFFFFFFFFFFFFFull, b2 = 0xFFFFFFFFFFFFFFFFull;
                #pragma unroll
                for (int nt = 0; nt < 8; nt++) {
                    float v0 = acc[mt][nt][hh * 2 + 0];
                    float v1 = acc[mt][nt][hh * 2 + 1];
                    int k0 = nt * 8 + qcol * 2;
                    float d0 = fmaf(-2.0f, v0, 2.0f);
                    float d1 = fmaf(-2.0f, v1, 2.0f);
                    float e0 = fast_exp2(v0 * TWO_LOG2E);
                    float e1 = fast_exp2(v1 * TWO_LOG2E);
                    probs[rowOff + k0] = e0;
                    probs[rowOff + k0 + 1] = e1;
                    s += e0 + e1;
                    m2insert(b1, b2, (((unsigned long long)enc_f(d0)) << 32) |
                                     (unsigned)(kBase + wc * 64 + k0));
                    m2insert(b1, b2, (((unsigned long long)enc_f(d1)) << 32) |
                                     (unsigned)(kBase + wc * 64 + k0 + 1));
                }
                s += __shfl_xor_sync(0xffffffffu, s, 1);
                s += __shfl_xor_sync(0xffffffffu, s, 2);
                #pragma unroll
                for (int o = 1; o <= 2; o <<= 1) {
                    unsigned long long o1 = __shfl_xor_sync(0xffffffffu, b1, o);
                    unsigned long long o2 = __shfl_xor_sync(0xffffffffu, b2, o);
                    m2merge(b1, b2, o1, o2);
                }
                if (qcol == 0) {
                    ssum[wc * 128 + rl] = s;
                    smin[(wc * 128 + rl) * 2 + 0] = b1;
                    smin[(wc * 128 + rl) * 2 + 1] = b2;
                }
            }
        }
        __syncthreads();
        if (tid < 128) {
            float s = 0.0f;
            unsigned long long b1 = 0xFFFFFFFFFFFFFFFFull, b2 = 0xFFFFFFFFFFFFFFFFull;
            #pragma unroll
            for (int w = 0; w < 4; w++) {
                s += ssum[w * 128 + tid];
                m2merge(b1, b2, smin[(w * 128 + tid) * 2 + 0], smin[(w * 128 + tid) * 2 + 1]);
            }
            atomicAdd(&g_rowsum[nBase + tid], s);
            size_t cb = (size_t)(nBase + tid) * 32 + (kBase >> 8) * 2;
            g_cand[cb + 0] = b1;
            g_cand[cb + 1] = b2;
        }
        __syncthreads();
        // reset acc for next tile
        #pragma unroll
        for (int mt = 0; mt < 2; mt++)
            #pragma unroll
            for (int nt = 0; nt < 8; nt++)
                #pragma unroll
                for (int e = 0; e < 4; e++) acc[mt][nt][e] = 0.0f;
    }
}

// --------------------------------------------------------------------------
// one warp per row: global min2 over 32 candidates; on near-tie, recompute
// candidate distances with a SEQUENTIAL fp32 fmaf chain over d ascending.
__global__ void finalize_kernel(float* __restrict__ out) {
    __shared__ float blockLoss;
    __shared__ int candList[8][32];
    __shared__ int candCnt[8];
    int lane = threadIdx.x & 31;
    int wid = threadIdx.x >> 5;
    if (threadIdx.x == 0) blockLoss = 0.0f;
    if (lane == 0) candCnt[wid] = 0;
    __syncthreads();
    int n = blockIdx.x * 8 + wid;

    const unsigned long long* cand = &g_cand[(size_t)n * 32];
    unsigned long long b1 = cand[lane];                 // one entry per lane
    unsigned long long b2 = 0xFFFFFFFFFFFFFFFFull;
    #pragma unroll
    for (int o = 16; o; o >>= 1) {
        unsigned long long o1 = __shfl_xor_sync(0xffffffffu, b1, o);
        unsigned long long o2 = __shfl_xor_sync(0xffffffffu, b2, o);
        m2merge(b1, b2, o1, o2);
    }
    float d1 = dec_f((unsigned)(b1 >> 32));
    float d2 = dec_f((unsigned)(b2 >> 32));
    int idx = (int)(unsigned)(b1 & 0xFFFFFFFFull);
    float dmin = d1;

    if (d2 - d1 < EPS_TIE) {
        unsigned long long e0 = cand[lane];
        float de0 = dec_f((unsigned)(e0 >> 32));
        if (de0 - d1 < EPS_TIE) {
            int p = atomicAdd(&candCnt[wid], 1);
            if (p < 32) candList[wid][p] = (int)(unsigned)(e0 & 0xFFFFFFFFull);
        }
        __syncwarp();
        int cnt = candCnt[wid];
        cnt = cnt > 32 ? 32 : cnt;
        unsigned long long mine = 0xFFFFFFFFFFFFFFFFull;
        if (lane < cnt) {
            int k = candList[wid][lane];
            const float* xr = &g_xn[(size_t)n * D_DIM];
            const float* wr = &g_wn[(size_t)k * D_DIM];
            float s = 0.0f;
            #pragma unroll 8
            for (int d = 0; d < D_DIM; d++)
                s = fmaf(xr[d], wr[d], s);
            float dist = 2.0f - 2.0f * s;
            mine = (((unsigned long long)enc_f(dist)) << 32) | (unsigned)k;
        }
        #pragma unroll
        for (int o = 16; o; o >>= 1) {
            unsigned long long v = __shfl_xor_sync(0xffffffffu, mine, o);
            mine = v < mine ? v : mine;
        }
        idx = (int)(unsigned)(mine & 0xFFFFFFFFull);
        dmin = dec_f((unsigned)(mine >> 32));
    }

    if (lane == 0) {
        out[OFF_IDX + n] = (float)idx;
        atomicAdd(&g_counts[idx], 1.0f);
        g_rowsum[n] = 1.0f / g_rowsum[n];
        atomicAdd(&blockLoss, dmin);
    }
    const float* src = &g_wn[(size_t)idx * D_DIM];
    float* dst = &out[OFF_QST + (size_t)n * D_DIM];
    #pragma unroll
    for (int u = 0; u < 8; u++) dst[lane + u * 32] = src[lane + u * 32];
    __syncthreads();
    if (threadIdx.x == 0) atomicAdd(&g_loss, blockLoss);
}

// --------------------------------------------------------------------------
__global__ void scale_kernel(float* __restrict__ out) {
    float* probs = out + OFF_PROBS;
    const size_t total = (size_t)N_ROWS * K_CODES;
    size_t gtid = (size_t)blockIdx.x * blockDim.x + threadIdx.x;
    if (gtid < 3) probs[gtid] *= g_rowsum[0];
    if (gtid == 3) probs[total - 1] *= g_rowsum[N_ROWS - 1];

    float4* p4 = reinterpret_cast<float4*>(probs + 3);
    const size_t total4 = (total - 3) / 4;
    const size_t stride = (size_t)gridDim.x * blockDim.x;
    for (size_t i = gtid; i < total4; i += stride) {
        size_t base = 3 + i * 4;
        float i0 = g_rowsum[(base + 0) >> 12];
        float i1 = g_rowsum[(base + 1) >> 12];
        float i2 = g_rowsum[(base + 2) >> 12];
        float i3 = g_rowsum[(base + 3) >> 12];
        float4 v = p4[i];
        v.x *= i0; v.y *= i1; v.z *= i2; v.w *= i3;
        p4[i] = v;
    }
}

// --------------------------------------------------------------------------
__global__ void scalars_kernel(float* __restrict__ out) {
    __shared__ float sEnt[256];
    __shared__ int sAct[256];
    int tid = threadIdx.x;
    float ent = 0.0f;
    int act = 0;
    for (int k = tid; k < K_CODES; k += 256) {
        float c = g_counts[k];
        float p = c * (1.0f / (float)N_ROWS);
        ent += p * logf(p + 1e-10f);
        act += (c > 0.0f) ? 1 : 0;
    }
    sEnt[tid] = ent;
    sAct[tid] = act;
    __syncthreads();
    for (int s = 128; s; s >>= 1) {
        if (tid < s) { sEnt[tid] += sEnt[tid + s]; sAct[tid] += sAct[tid + s]; }
        __syncthreads();
    }
    if (tid == 0) {
        out[OFF_LOSS] = 0.25f * g_loss / (float)((size_t)N_ROWS * D_DIM);
        out[OFF_PERP] = expf(-sEnt[0]);
        out[OFF_ACT]  = (float)sAct[0];
        out[OFF_USE]  = (float)sAct[0] * (100.0f / (float)K_CODES);
    }
}

// --------------------------------------------------------------------------
extern "C" void kernel_launch(void* const* d_in, const int* in_sizes, int n_in,
                              void* d_out, int out_size) {
    const float* inp = (const float*)d_in[0];   // (16,2048,256) fp32
    const float* w   = (const float*)d_in[1];   // (4096,256) fp32
    float* out = (float*)d_out;

    int dev = 0, sms = 148;
    cudaGetDevice(&dev);
    cudaDeviceGetAttribute(&sms, cudaDevAttrMultiProcessorCount, dev);
    if (sms <= 0 || sms > NTILES) sms = 148;

    cudaFuncSetAttribute(gemm_kernel, cudaFuncAttributeMaxDynamicSharedMemorySize, GEMM_SMEM);

    init_kernel<<<128, 256>>>();
    normsplit_kernel<<<K_CODES / 8, 256>>>(w, K_CODES, 0);
    normsplit_kernel<<<N_ROWS / 8, 256>>>(inp, N_ROWS, 1);
    gemm_kernel<<<sms, 512, GEMM_SMEM>>>(out);
    finalize_kernel<<<N_ROWS / 8, 256>>>(out);
    scale_kernel<<<4096, 256>>>(out);
    scalars_kernel<<<1, 256>>>(out);
}

// round 13
// speedup vs baseline: 1.1571x; 1.0273x over previous
#include <cuda_runtime.h>
#include <cuda_bf16.h>
#include <math.h>
#include <stdint.h>

#define N_ROWS 32768
#define D_DIM  256
#define K_CODES 4096
#define NTILES 4096          // 256 n-tiles x 16 k-tiles
#define EPS_TIE 5e-4f

// ---- output layout (floats) ----
#define OFF_LOSS  0ull
#define OFF_QST   1ull
#define OFF_PROBS (1ull + (unsigned long long)N_ROWS * D_DIM)
#define OFF_PERP  (OFF_PROBS + (unsigned long long)N_ROWS * K_CODES)
#define OFF_IDX   (OFF_PERP + 1ull)
#define OFF_ACT   (OFF_IDX + N_ROWS)
#define OFF_USE   (OFF_ACT + 1ull)

// ---- scratch (static __device__: allocation-free) ----
static __device__ __align__(16) float g_wn[K_CODES * D_DIM];  // normalized fp32
static __device__ __align__(16) float g_xn[N_ROWS * D_DIM];   // normalized fp32
static __device__ float g_rowsum[N_ROWS];
static __device__ unsigned long long g_cand[(size_t)N_ROWS * 32]; // per (row, kTile) min2
static __device__ float g_counts[K_CODES];
static __device__ float g_loss;

// --------------------------------------------------------------------------
__device__ __forceinline__ uint32_t smem_u32(const void* p) {
    uint32_t a;
    asm("{ .reg .u64 t; cvta.to.shared.u64 t, %1; cvt.u32.u64 %0, t; }" : "=r"(a) : "l"(p));
    return a;
}
#define CP_ASYNC16(dst, src) \
    asm volatile("cp.async.cg.shared.global [%0], [%1], 16;" :: "r"(dst), "l"(src))
#define CP_COMMIT() asm volatile("cp.async.commit_group;" ::: "memory")
#define CP_WAIT1()  asm volatile("cp.async.wait_group 1;" ::: "memory")

__device__ __forceinline__ void ldsm_x4(uint32_t* r, uint32_t addr) {
    asm volatile("ldmatrix.sync.aligned.m8n8.x4.shared.b16 {%0,%1,%2,%3}, [%4];"
                 : "=r"(r[0]), "=r"(r[1]), "=r"(r[2]), "=r"(r[3]) : "r"(addr));
}
// tf32 MMA m16n8k8, fp32 accum (baseline sm_80 PTX). Inputs are fp32 bit
// patterns; tensor core uses tf32 precision (low mantissa bits ignored).
__device__ __forceinline__ void mma1688(float* d, const uint32_t* a, const uint32_t* b) {
    asm volatile("mma.sync.aligned.m16n8k8.row.col.f32.tf32.tf32.f32 "
                 "{%0,%1,%2,%3},{%4,%5,%6,%7},{%8,%9},{%0,%1,%2,%3};"
                 : "+f"(d[0]), "+f"(d[1]), "+f"(d[2]), "+f"(d[3])
                 : "r"(a[0]), "r"(a[1]), "r"(a[2]), "r"(a[3]), "r"(b[0]), "r"(b[1]));
}
// 2^t via FFMA-only poly (no MUFU). |rel err| < 2e-5.
__device__ __forceinline__ float fast_exp2(float t) {
    float fi = floorf(t);
    float f = t - fi;
    float p = 1.5403530e-4f;
    p = fmaf(p, f, 1.3333558e-3f);
    p = fmaf(p, f, 9.6181291e-3f);
    p = fmaf(p, f, 5.5504109e-2f);
    p = fmaf(p, f, 2.4022651e-1f);
    p = fmaf(p, f, 6.9314718e-1f);
    p = fmaf(p, f, 1.0f);
    return __int_as_float(__float_as_int(p) + (((int)fi) << 23));
}
__device__ __forceinline__ unsigned enc_f(float x) {
    unsigned u = __float_as_uint(x);
    return (u & 0x80000000u) ? ~u : (u | 0x80000000u);
}
__device__ __forceinline__ float dec_f(unsigned e) {
    return (e & 0x80000000u) ? __uint_as_float(e & 0x7FFFFFFFu) : __uint_as_float(~e);
}
__device__ __forceinline__ void m2merge(unsigned long long& a1, unsigned long long& a2,
                                        unsigned long long b1, unsigned long long b2) {
    unsigned long long lo = a1 < b1 ? a1 : b1;
    unsigned long long hi = a1 < b1 ? b1 : a1;
    unsigned long long mn2 = a2 < b2 ? a2 : b2;
    a1 = lo;
    a2 = hi < mn2 ? hi : mn2;
}
__device__ __forceinline__ void m2insert(unsigned long long& a1, unsigned long long& a2,
                                         unsigned long long v) {
    if (v < a1) { a2 = a1; a1 = v; }
    else if (v < a2) { a2 = v; }
}

// --------------------------------------------------------------------------
__global__ void init_kernel() {
    int i = blockIdx.x * blockDim.x + threadIdx.x;
    if (i < N_ROWS) g_rowsum[i] = 0.0f;
    if (i < K_CODES) g_counts[i] = 0.0f;
    if (i == 0) g_loss = 0.0f;
}

// --------------------------------------------------------------------------
// one warp per row: l2-normalize, store normalized fp32
__global__ void normsplit_kernel(const float* __restrict__ src, int rows, int which) {
    int warp = (blockIdx.x * blockDim.x + threadIdx.x) >> 5;
    int lane = threadIdx.x & 31;
    if (warp >= rows) return;
    const float4* s4 = reinterpret_cast<const float4*>(src + (size_t)warp * D_DIM);
    float4 a = s4[lane];
    float4 b = s4[lane + 32];
    float ss = a.x*a.x + a.y*a.y + a.z*a.z + a.w*a.w
             + b.x*b.x + b.y*b.y + b.z*b.z + b.w*b.w;
    #pragma unroll
    for (int o = 16; o; o >>= 1) ss += __shfl_xor_sync(0xffffffffu, ss, o);
    float sc = 1.0f / fmaxf(sqrtf(ss), 1e-12f);
    a.x *= sc; a.y *= sc; a.z *= sc; a.w *= sc;
    b.x *= sc; b.y *= sc; b.z *= sc; b.w *= sc;
    float4* d4 = reinterpret_cast<float4*>((which ? g_xn : g_wn) + (size_t)warp * D_DIM);
    d4[lane] = a;
    d4[lane + 32] = b;
}

// --------------------------------------------------------------------------
// Persistent tf32 mma.sync GEMM, BK=64, 2-stage 96KB ring.
// CTA tile 128(n) x 256(k); 512 threads, 16 warps (4 wr x 4 wc), warp 32x64.
// smem tile: 256B/row (16 x 16B slots), slot s stored at s ^ (row & 7).
#define STAGE_SZ  98304          // A 32KB (128 rows x 256B) + B 64KB (256 rows)
#define TILE_Aofs 0
#define TILE_Bofs 32768
#define RED_OFF   (2 * STAGE_SZ)
#define GEMM_SMEM (2 * STAGE_SZ + 10240 + 1024)
#define TWO_LOG2E 2.8853900817779268f

struct FragT {
    uint32_t a[2][4];
    uint32_t b[4][4];
};

__device__ __forceinline__ void load_frags_t(FragT& f, uint32_t st, int ks,
                                             int wr, int wc, int lane) {
    const int r8 = lane & 7;
    #pragma unroll
    for (int mt = 0; mt < 2; mt++) {
        int row = wr * 32 + mt * 16 + r8 + ((lane >> 3) & 1) * 8;
        int ls = ks * 2 + (lane >> 4);
        ldsm_x4(f.a[mt], st + TILE_Aofs + row * 256 + (((ls ^ (row & 7)) & 15) << 4));
    }
    #pragma unroll
    for (int pr = 0; pr < 4; pr++) {
        int row = wc * 64 + pr * 16 + r8 + (lane >> 4) * 8;
        int ls = ks * 2 + ((lane >> 3) & 1);
        ldsm_x4(f.b[pr], st + TILE_Bofs + row * 256 + (((ls ^ (row & 7)) & 15) << 4));
    }
}

__device__ __forceinline__ void mma_all_t(float (&acc)[2][8][4], const FragT& f) {
    #pragma unroll
    for (int mt = 0; mt < 2; mt++)
        #pragma unroll
        for (int nt = 0; nt < 8; nt++)
            mma1688(acc[mt][nt], f.a[mt], &f.b[nt >> 1][(nt & 1) * 2]);
}

// producer: copy BK=64 chunk pc (0..3) of tile pt into stage st
__device__ __forceinline__ void produce_chunk(uint32_t st, int pt, int pc, int tid) {
    if (pt < NTILES) {
        int nB = (pt >> 4) * 128, kB = (pt & 15) * 256;
        #pragma unroll
        for (int rep = 0; rep < 4; rep++) {      // A: 128 rows x 16 slots = 2048
            int idx = tid + rep * 512;
            int row = idx >> 4, slot = idx & 15;
            uint32_t doff = (uint32_t)(row * 256 + ((slot ^ (row & 7)) << 4));
            CP_ASYNC16(st + TILE_Aofs + doff,
                       g_xn + (size_t)(nB + row) * D_DIM + pc * 64 + slot * 4);
        }
        #pragma unroll
        for (int rep = 0; rep < 8; rep++) {      // B: 256 rows x 16 slots = 4096
            int idx = tid + rep * 512;
            int row = idx >> 4, slot = idx & 15;
            uint32_t doff = (uint32_t)(row * 256 + ((slot ^ (row & 7)) << 4));
            CP_ASYNC16(st + TILE_Bofs + doff,
                       g_wn + (size_t)(kB + row) * D_DIM + pc * 64 + slot * 4);
        }
    }
    CP_COMMIT();
}

__global__ __launch_bounds__(512, 1) void gemm_kernel(float* __restrict__ out) {
    extern __shared__ char smraw[];
    uint32_t sb = (smem_u32(smraw) + 1023u) & ~1023u;
    char* smem = smraw + (sb - smem_u32(smraw));

    const int tid = threadIdx.x;
    const int wid = tid >> 5;
    const int lane = tid & 31;
    const int wr = wid >> 2;     // 0..3 -> 32 n-rows each
    const int wc = wid & 3;      // 0..3 -> 64 k-cols each
    const int stride = gridDim.x;

    float acc[2][8][4];
    #pragma unroll
    for (int mt = 0; mt < 2; mt++)
        #pragma unroll
        for (int nt = 0; nt < 8; nt++)
            #pragma unroll
            for (int e = 0; e < 4; e++) acc[mt][nt][e] = 0.0f;

    FragT fr;

    // producer: 2 stages in flight (4 chunks per tile)
    int pt = blockIdx.x, pc = 0;
    #pragma unroll
    for (int s = 0; s < 2; s++) {
        produce_chunk(sb + s * STAGE_SZ, pt, pc, tid);
        if (++pc == 4) { pc = 0; pt += stride; }
    }

    int gphase = 0;
    float* probs = out + OFF_PROBS;
    const int qrow = lane >> 2;
    const int qcol = lane & 3;
    float* ssum = reinterpret_cast<float*>(smem + RED_OFF);                         // [4][128]
    unsigned long long* smin = reinterpret_cast<unsigned long long*>(smem + RED_OFF + 2048); // [4][128][2]

    for (int t = blockIdx.x; t < NTILES; t += stride) {
        const int nBase = (t >> 4) * 128;
        const int kBase = (t & 15) * 256;

        for (int c = 0; c < 4; c++) {
            uint32_t st = sb + gphase * STAGE_SZ;
            CP_WAIT1();
            __syncthreads();
            #pragma unroll
            for (int ks = 0; ks < 8; ks++) {
                load_frags_t(fr, st, ks, wr, wc, lane);
                mma_all_t(acc, fr);
            }
            __syncthreads();
            produce_chunk(st, pt, pc, tid);
            if (++pc == 4) { pc = 0; pt += stride; }
            gphase ^= 1;
        }

        // ---- epilogue: probs, rowsum, per-CTA min2 candidates ----
        #pragma unroll
        for (int mt = 0; mt < 2; mt++) {
            #pragma unroll
            for (int hh = 0; hh < 2; hh++) {
                int rl = wr * 32 + mt * 16 + hh * 8 + qrow;
                size_t rowOff = (size_t)(nBase + rl) * K_CODES + kBase + wc * 64;
                float s = 0.0f;
                unsigned long long b1 = 0xFFFFFFFFFFFFFFFFull, b2 = 0xFFFFFFFFFFFFFFFFull;
                #pragma unroll
                for (int nt = 0; nt < 8; nt++) {
                    float v0 = acc[mt][nt][hh * 2 + 0];
                    float v1 = acc[mt][nt][hh * 2 + 1];
                    int k0 = nt * 8 + qcol * 2;
                    float d0 = fmaf(-2.0f, v0, 2.0f);
                    float d1 = fmaf(-2.0f, v1, 2.0f);
                    float e0 = fast_exp2(v0 * TWO_LOG2E);
                    float e1 = fast_exp2(v1 * TWO_LOG2E);
                    probs[rowOff + k0] = e0;
                    probs[rowOff + k0 + 1] = e1;
                    s += e0 + e1;
                    m2insert(b1, b2, (((unsigned long long)enc_f(d0)) << 32) |
                                     (unsigned)(kBase + wc * 64 + k0));
                    m2insert(b1, b2, (((unsigned long long)enc_f(d1)) << 32) |
                                     (unsigned)(kBase + wc * 64 + k0 + 1));
                }
                s += __shfl_xor_sync(0xffffffffu, s, 1);
                s += __shfl_xor_sync(0xffffffffu, s, 2);
                #pragma unroll
                for (int o = 1; o <= 2; o <<= 1) {
                    unsigned long long o1 = __shfl_xor_sync(0xffffffffu, b1, o);
                    unsigned long long o2 = __shfl_xor_sync(0xffffffffu, b2, o);
                    m2merge(b1, b2, o1, o2);
                }
                if (qcol == 0) {
                    ssum[wc * 128 + rl] = s;
                    smin[(wc * 128 + rl) * 2 + 0] = b1;
                    smin[(wc * 128 + rl) * 2 + 1] = b2;
                }
            }
        }
        __syncthreads();
        if (tid < 128) {
            float s = 0.0f;
            unsigned long long b1 = 0xFFFFFFFFFFFFFFFFull, b2 = 0xFFFFFFFFFFFFFFFFull;
            #pragma unroll
            for (int w = 0; w < 4; w++) {
                s += ssum[w * 128 + tid];
                m2merge(b1, b2, smin[(w * 128 + tid) * 2 + 0], smin[(w * 128 + tid) * 2 + 1]);
            }
            atomicAdd(&g_rowsum[nBase + tid], s);
            size_t cb = (size_t)(nBase + tid) * 32 + (kBase >> 8) * 2;
            g_cand[cb + 0] = b1;
            g_cand[cb + 1] = b2;
        }
        __syncthreads();
        // reset acc for next tile
        #pragma unroll
        for (int mt = 0; mt < 2; mt++)
            #pragma unroll
            for (int nt = 0; nt < 8; nt++)
                #pragma unroll
                for (int e = 0; e < 4; e++) acc[mt][nt][e] = 0.0f;
    }
}

// --------------------------------------------------------------------------
// one warp per row: global min2 over 32 candidates; on near-tie, recompute
// candidate distances with a SEQUENTIAL fp32 fmaf chain over d ascending.
__global__ void finalize_kernel(float* __restrict__ out) {
    __shared__ float blockLoss;
    __shared__ int candList[8][32];
    __shared__ int candCnt[8];
    int lane = threadIdx.x & 31;
    int wid = threadIdx.x >> 5;
    if (threadIdx.x == 0) blockLoss = 0.0f;
    if (lane == 0) candCnt[wid] = 0;
    __syncthreads();
    int n = blockIdx.x * 8 + wid;

    const unsigned long long* cand = &g_cand[(size_t)n * 32];
    unsigned long long b1 = cand[lane];                 // one entry per lane
    unsigned long long b2 = 0xFFFFFFFFFFFFFFFFull;
    #pragma unroll
    for (int o = 16; o; o >>= 1) {
        unsigned long long o1 = __shfl_xor_sync(0xffffffffu, b1, o);
        unsigned long long o2 = __shfl_xor_sync(0xffffffffu, b2, o);
        m2merge(b1, b2, o1, o2);
    }
    float d1 = dec_f((unsigned)(b1 >> 32));
    float d2 = dec_f((unsigned)(b2 >> 32));
    int idx = (int)(unsigned)(b1 & 0xFFFFFFFFull);
    float dmin = d1;

    if (d2 - d1 < EPS_TIE) {
        unsigned long long e0 = cand[lane];
        float de0 = dec_f((unsigned)(e0 >> 32));
        if (de0 - d1 < EPS_TIE) {
            int p = atomicAdd(&candCnt[wid], 1);
            if (p < 32) candList[wid][p] = (int)(unsigned)(e0 & 0xFFFFFFFFull);
        }
        __syncwarp();
        int cnt = candCnt[wid];
        cnt = cnt > 32 ? 32 : cnt;
        unsigned long long mine = 0xFFFFFFFFFFFFFFFFull;
        if (lane < cnt) {
            int k = candList[wid][lane];
            const float* xr = &g_xn[(size_t)n * D_DIM];
            const float* wr = &g_wn[(size_t)k * D_DIM];
            float s = 0.0f;
            #pragma unroll 8
            for (int d = 0; d < D_DIM; d++)
                s = fmaf(xr[d], wr[d], s);
            float dist = 2.0f - 2.0f * s;
            mine = (((unsigned long long)enc_f(dist)) << 32) | (unsigned)k;
        }
        #pragma unroll
        for (int o = 16; o; o >>= 1) {
            unsigned long long v = __shfl_xor_sync(0xffffffffu, mine, o);
            mine = v < mine ? v : mine;
        }
        idx = (int)(unsigned)(mine & 0xFFFFFFFFull);
        dmin = dec_f((unsigned)(mine >> 32));
    }

    if (lane == 0) {
        out[OFF_IDX + n] = (float)idx;
        atomicAdd(&g_counts[idx], 1.0f);
        g_rowsum[n] = 1.0f / g_rowsum[n];
        atomicAdd(&blockLoss, dmin);
    }
    const float* src = &g_wn[(size_t)idx * D_DIM];
    float* dst = &out[OFF_QST + (size_t)n * D_DIM];
    #pragma unroll
    for (int u = 0; u < 8; u++) dst[lane + u * 32] = src[lane + u * 32];
    __syncthreads();
    if (threadIdx.x == 0) atomicAdd(&g_loss, blockLoss);
}

// --------------------------------------------------------------------------
__global__ void scale_kernel(float* __restrict__ out) {
    float* probs = out + OFF_PROBS;
    const size_t total = (size_t)N_ROWS * K_CODES;
    size_t gtid = (size_t)blockIdx.x * blockDim.x + threadIdx.x;
    if (gtid < 3) probs[gtid] *= g_rowsum[0];
    if (gtid == 3) probs[total - 1] *= g_rowsum[N_ROWS - 1];

    float4* p4 = reinterpret_cast<float4*>(probs + 3);
    const size_t total4 = (total - 3) / 4;
    const size_t stride = (size_t)gridDim.x * blockDim.x;
    for (size_t i = gtid; i < total4; i += stride) {
        size_t base = 3 + i * 4;
        float i0 = g_rowsum[(base + 0) >> 12];
        float i1 = g_rowsum[(base + 1) >> 12];
        float i2 = g_rowsum[(base + 2) >> 12];
        float i3 = g_rowsum[(base + 3) >> 12];
        float4 v = p4[i];
        v.x *= i0; v.y *= i1; v.z *= i2; v.w *= i3;
        p4[i] = v;
    }
}

// --------------------------------------------------------------------------
__global__ void scalars_kernel(float* __restrict__ out) {
    __shared__ float sEnt[256];
    __shared__ int sAct[256];
    int tid = threadIdx.x;
    float ent = 0.0f;
    int act = 0;
    for (int k = tid; k < K_CODES; k += 256) {
        float c = g_counts[k];
        float p = c * (1.0f / (float)N_ROWS);
        ent += p * logf(p + 1e-10f);
        act += (c > 0.0f) ? 1 : 0;
    }
    sEnt[tid] = ent;
    sAct[tid] = act;
    __syncthreads();
    for (int s = 128; s; s >>= 1) {
        if (tid < s) { sEnt[tid] += sEnt[tid + s]; sAct[tid] += sAct[tid + s]; }
        __syncthreads();
    }
    if (tid == 0) {
        out[OFF_LOSS] = 0.25f * g_loss / (float)((size_t)N_ROWS * D_DIM);
        out[OFF_PERP] = expf(-sEnt[0]);
        out[OFF_ACT]  = (float)sAct[0];
        out[OFF_USE]  = (float)sAct[0] * (100.0f / (float)K_CODES);
    }
}

// --------------------------------------------------------------------------
extern "C" void kernel_launch(void* const* d_in, const int* in_sizes, int n_in,
                              void* d_out, int out_size) {
    const float* inp = (const float*)d_in[0];   // (16,2048,256) fp32
    const float* w   = (const float*)d_in[1];   // (4096,256) fp32
    float* out = (float*)d_out;

    int dev = 0, sms = 148;
    cudaGetDevice(&dev);
    cudaDeviceGetAttribute(&sms, cudaDevAttrMultiProcessorCount, dev);
    if (sms <= 0 || sms > NTILES) sms = 148;

    cudaFuncSetAttribute(gemm_kernel, cudaFuncAttributeMaxDynamicSharedMemorySize, GEMM_SMEM);

    init_kernel<<<128, 256>>>();
    normsplit_kernel<<<K_CODES / 8, 256>>>(w, K_CODES, 0);
    normsplit_kernel<<<N_ROWS / 8, 256>>>(inp, N_ROWS, 1);
    gemm_kernel<<<sms, 512, GEMM_SMEM>>>(out);
    finalize_kernel<<<N_ROWS / 8, 256>>>(out);
    scale_kernel<<<4096, 256>>>(out);
    scalars_kernel<<<1, 256>>>(out);
}

// round 14
// speedup vs baseline: 1.1874x; 1.0262x over previous
#include <cuda_runtime.h>
#include <cuda_bf16.h>
#include <math.h>
#include <stdint.h>

#define N_ROWS 32768
#define D_DIM  256
#define K_CODES 4096
#define NTILES 4096          // 256 n-tiles x 16 k-tiles
#define EPS_TIE 5e-4f

// ---- output layout (floats) ----
#define OFF_LOSS  0ull
#define OFF_QST   1ull
#define OFF_PROBS (1ull + (unsigned long long)N_ROWS * D_DIM)
#define OFF_PERP  (OFF_PROBS + (unsigned long long)N_ROWS * K_CODES)
#define OFF_IDX   (OFF_PERP + 1ull)
#define OFF_ACT   (OFF_IDX + N_ROWS)
#define OFF_USE   (OFF_ACT + 1ull)

// ---- scratch (static __device__: allocation-free) ----
static __device__ __align__(16) float g_wn[K_CODES * D_DIM];  // normalized fp32
static __device__ __align__(16) float g_xn[N_ROWS * D_DIM];   // normalized fp32
static __device__ float g_rowsum[N_ROWS];
static __device__ unsigned long long g_cand[(size_t)N_ROWS * 32]; // per (row, kTile) min2
static __device__ float g_counts[K_CODES];
static __device__ float g_loss;

// --------------------------------------------------------------------------
__device__ __forceinline__ uint32_t smem_u32(const void* p) {
    uint32_t a;
    asm("{ .reg .u64 t; cvta.to.shared.u64 t, %1; cvt.u32.u64 %0, t; }" : "=r"(a) : "l"(p));
    return a;
}
#define CP_ASYNC16(dst, src) \
    asm volatile("cp.async.cg.shared.global [%0], [%1], 16;" :: "r"(dst), "l"(src))
#define CP_COMMIT() asm volatile("cp.async.commit_group;" ::: "memory")
#define CP_WAIT2()  asm volatile("cp.async.wait_group 2;" ::: "memory")

__device__ __forceinline__ void ldsm_x4(uint32_t* r, uint32_t addr) {
    asm volatile("ldmatrix.sync.aligned.m8n8.x4.shared.b16 {%0,%1,%2,%3}, [%4];"
                 : "=r"(r[0]), "=r"(r[1]), "=r"(r[2]), "=r"(r[3]) : "r"(addr));
}
// tf32 MMA m16n8k8, fp32 accum (baseline sm_80 PTX). Inputs are fp32 bit
// patterns; tensor core uses tf32 precision (low mantissa bits ignored).
__device__ __forceinline__ void mma1688(float* d, const uint32_t* a, const uint32_t* b) {
    asm volatile("mma.sync.aligned.m16n8k8.row.col.f32.tf32.tf32.f32 "
                 "{%0,%1,%2,%3},{%4,%5,%6,%7},{%8,%9},{%0,%1,%2,%3};"
                 : "+f"(d[0]), "+f"(d[1]), "+f"(d[2]), "+f"(d[3])
                 : "r"(a[0]), "r"(a[1]), "r"(a[2]), "r"(a[3]), "r"(b[0]), "r"(b[1]));
}
// 2^t via FFMA-only poly (no MUFU). |rel err| < 2e-5.
__device__ __forceinline__ float fast_exp2(float t) {
    float fi = floorf(t);
    float f = t - fi;
    float p = 1.5403530e-4f;
    p = fmaf(p, f, 1.3333558e-3f);
    p = fmaf(p, f, 9.6181291e-3f);
    p = fmaf(p, f, 5.5504109e-2f);
    p = fmaf(p, f, 2.4022651e-1f);
    p = fmaf(p, f, 6.9314718e-1f);
    p = fmaf(p, f, 1.0f);
    return __int_as_float(__float_as_int(p) + (((int)fi) << 23));
}
__device__ __forceinline__ unsigned enc_f(float x) {
    unsigned u = __float_as_uint(x);
    return (u & 0x80000000u) ? ~u : (u | 0x80000000u);
}
__device__ __forceinline__ float dec_f(unsigned e) {
    return (e & 0x80000000u) ? __uint_as_float(e & 0x7FFFFFFFu) : __uint_as_float(~e);
}
__device__ __forceinline__ void m2merge(unsigned long long& a1, unsigned long long& a2,
                                        unsigned long long b1, unsigned long long b2) {
    unsigned long long lo = a1 < b1 ? a1 : b1;
    unsigned long long hi = a1 < b1 ? b1 : a1;
    unsigned long long mn2 = a2 < b2 ? a2 : b2;
    a1 = lo;
    a2 = hi < mn2 ? hi : mn2;
}
__device__ __forceinline__ void m2insert(unsigned long long& a1, unsigned long long& a2,
                                         unsigned long long v) {
    if (v < a1) { a2 = a1; a1 = v; }
    else if (v < a2) { a2 = v; }
}

// --------------------------------------------------------------------------
__global__ void init_kernel() {
    int i = blockIdx.x * blockDim.x + threadIdx.x;
    if (i < N_ROWS) g_rowsum[i] = 0.0f;
    if (i < K_CODES) g_counts[i] = 0.0f;
    if (i == 0) g_loss = 0.0f;
}

// --------------------------------------------------------------------------
// one warp per row: l2-normalize, store normalized fp32
__global__ void normsplit_kernel(const float* __restrict__ src, int rows, int which) {
    int warp = (blockIdx.x * blockDim.x + threadIdx.x) >> 5;
    int lane = threadIdx.x & 31;
    if (warp >= rows) return;
    const float4* s4 = reinterpret_cast<const float4*>(src + (size_t)warp * D_DIM);
    float4 a = s4[lane];
    float4 b = s4[lane + 32];
    float ss = a.x*a.x + a.y*a.y + a.z*a.z + a.w*a.w
             + b.x*b.x + b.y*b.y + b.z*b.z + b.w*b.w;
    #pragma unroll
    for (int o = 16; o; o >>= 1) ss += __shfl_xor_sync(0xffffffffu, ss, o);
    float sc = 1.0f / fmaxf(sqrtf(ss), 1e-12f);
    a.x *= sc; a.y *= sc; a.z *= sc; a.w *= sc;
    b.x *= sc; b.y *= sc; b.z *= sc; b.w *= sc;
    float4* d4 = reinterpret_cast<float4*>((which ? g_xn : g_wn) + (size_t)warp * D_DIM);
    d4[lane] = a;
    d4[lane + 32] = b;
}

// --------------------------------------------------------------------------
// Persistent tf32 mma.sync GEMM, BK=32, 4-stage ring, ONE syncthreads/chunk.
// CTA tile 128(n) x 256(k); 512 threads, 16 warps (4 wr x 4 wc), warp 32x64.
// smem tile: 128B/row (8 x 16B slots), slot s stored at s ^ (row & 7).
// LDSM addresses: base ^ (ks<<5), base precomputed per thread.
#define STAGE_SZ  49152          // A 16KB (128 rows x 128B) + B 32KB (256 rows)
#define TILE_Aofs 0
#define TILE_Bofs 16384
#define RED_OFF   (4 * STAGE_SZ)
#define GEMM_SMEM (4 * STAGE_SZ + 10240 + 1024)
#define TWO_LOG2E 2.8853900817779268f

struct FragT {
    uint32_t a[2][4];
    uint32_t b[4][4];
};

__device__ __forceinline__ void load_frags_t(FragT& f, uint32_t st, int ks,
                                             const uint32_t* baseA,
                                             const uint32_t* baseB) {
    const uint32_t kx = (uint32_t)(ks << 5);
    #pragma unroll
    for (int mt = 0; mt < 2; mt++)
        ldsm_x4(f.a[mt], st + (baseA[mt] ^ kx));
    #pragma unroll
    for (int pr = 0; pr < 4; pr++)
        ldsm_x4(f.b[pr], st + (baseB[pr] ^ kx));
}

__device__ __forceinline__ void mma_all_t(float (&acc)[2][8][4], const FragT& f) {
    #pragma unroll
    for (int mt = 0; mt < 2; mt++)
        #pragma unroll
        for (int nt = 0; nt < 8; nt++)
            mma1688(acc[mt][nt], f.a[mt], &f.b[nt >> 1][(nt & 1) * 2]);
}

// producer: copy BK=32 chunk pc (0..7) of tile pt into stage st
__device__ __forceinline__ void produce_chunk(uint32_t st, int pt, int pc, int tid) {
    if (pt < NTILES) {
        int nB = (pt >> 4) * 128, kB = (pt & 15) * 256;
        #pragma unroll
        for (int rep = 0; rep < 2; rep++) {      // A: 128 rows x 8 slots = 1024
            int idx = tid + rep * 512;
            int row = idx >> 3, slot = idx & 7;
            uint32_t doff = (uint32_t)(row * 128 + ((slot ^ (row & 7)) << 4));
            CP_ASYNC16(st + TILE_Aofs + doff,
                       g_xn + (size_t)(nB + row) * D_DIM + pc * 32 + slot * 4);
        }
        #pragma unroll
        for (int rep = 0; rep < 4; rep++) {      // B: 256 rows x 8 slots = 2048
            int idx = tid + rep * 512;
            int row = idx >> 3, slot = idx & 7;
            uint32_t doff = (uint32_t)(row * 128 + ((slot ^ (row & 7)) << 4));
            CP_ASYNC16(st + TILE_Bofs + doff,
                       g_wn + (size_t)(kB + row) * D_DIM + pc * 32 + slot * 4);
        }
    }
    CP_COMMIT();
}

__global__ __launch_bounds__(512, 1) void gemm_kernel(float* __restrict__ out) {
    extern __shared__ char smraw[];
    uint32_t sb = (smem_u32(smraw) + 1023u) & ~1023u;
    char* smem = smraw + (sb - smem_u32(smraw));

    const int tid = threadIdx.x;
    const int wid = tid >> 5;
    const int lane = tid & 31;
    const int wr = wid >> 2;     // 0..3 -> 32 n-rows each
    const int wc = wid & 3;      // 0..3 -> 64 k-cols each
    const int stride = gridDim.x;

    // precomputed fragment base offsets (slot XOR folded in)
    uint32_t baseA[2], baseB[4];
    {
        int r16 = lane & 15, hA = lane >> 4;
        #pragma unroll
        for (int mt = 0; mt < 2; mt++) {
            int row = wr * 32 + mt * 16 + r16;
            baseA[mt] = TILE_Aofs + row * 128 + (((hA ^ (row & 7)) & 7) << 4);
        }
        int r8 = lane & 7, hiB = (lane >> 4) * 8, hB = (lane >> 3) & 1;
        #pragma unroll
        for (int pr = 0; pr < 4; pr++) {
            int row = wc * 64 + pr * 16 + r8 + hiB;
            baseB[pr] = TILE_Bofs + row * 128 + (((hB ^ (row & 7)) & 7) << 4);
        }
    }

    float acc[2][8][4];
    #pragma unroll
    for (int mt = 0; mt < 2; mt++)
        #pragma unroll
        for (int nt = 0; nt < 8; nt++)
            #pragma unroll
            for (int e = 0; e < 4; e++) acc[mt][nt][e] = 0.0f;

    FragT fr;

    // producer: 3 chunks in flight into stages 0,1,2 of the 4-stage ring
    int pt = blockIdx.x, pc = 0;
    #pragma unroll
    for (int s = 0; s < 3; s++) {
        produce_chunk(sb + s * STAGE_SZ, pt, pc, tid);
        if (++pc == 8) { pc = 0; pt += stride; }
    }

    int gphase = 0;
    float* probs = out + OFF_PROBS;
    const int qrow = lane >> 2;
    const int qcol = lane & 3;
    float* ssum = reinterpret_cast<float*>(smem + RED_OFF);                         // [4][128]
    unsigned long long* smin = reinterpret_cast<unsigned long long*>(smem + RED_OFF + 2048); // [4][128][2]

    for (int t = blockIdx.x; t < NTILES; t += stride) {
        const int nBase = (t >> 4) * 128;
        const int kBase = (t & 15) * 256;

        for (int c = 0; c < 8; c++) {
            uint32_t st = sb + gphase * STAGE_SZ;
            CP_WAIT2();            // this chunk's stage complete (<=2 younger pending)
            __syncthreads();       // also: all warps finished reading stage (gphase+3)%4
            // refill the stage consumed last chunk (safe: barrier above)
            produce_chunk(sb + ((gphase + 3) & 3) * STAGE_SZ, pt, pc, tid);
            if (++pc == 8) { pc = 0; pt += stride; }
            #pragma unroll
            for (int ks = 0; ks < 4; ks++) {
                load_frags_t(fr, st, ks, baseA, baseB);
                mma_all_t(acc, fr);
            }
            gphase = (gphase + 1) & 3;
        }

        // ---- epilogue: probs, rowsum, per-CTA min2 candidates ----
        #pragma unroll
        for (int mt = 0; mt < 2; mt++) {
            #pragma unroll
            for (int hh = 0; hh < 2; hh++) {
                int rl = wr * 32 + mt * 16 + hh * 8 + qrow;
                size_t rowOff = (size_t)(nBase + rl) * K_CODES + kBase + wc * 64;
                float s = 0.0f;
                unsigned long long b1 = 0xFFFFFFFFFFFFFFFFull, b2 = 0xFFFFFFFFFFFFFFFFull;
                #pragma unroll
                for (int nt = 0; nt < 8; nt++) {
                    float v0 = acc[mt][nt][hh * 2 + 0];
                    float v1 = acc[mt][nt][hh * 2 + 1];
                    int k0 = nt * 8 + qcol * 2;
                    float d0 = fmaf(-2.0f, v0, 2.0f);
                    float d1 = fmaf(-2.0f, v1, 2.0f);
                    float e0 = fast_exp2(v0 * TWO_LOG2E);
                    float e1 = fast_exp2(v1 * TWO_LOG2E);
                    probs[rowOff + k0] = e0;
                    probs[rowOff + k0 + 1] = e1;
                    s += e0 + e1;
                    m2insert(b1, b2, (((unsigned long long)enc_f(d0)) << 32) |
                                     (unsigned)(kBase + wc * 64 + k0));
                    m2insert(b1, b2, (((unsigned long long)enc_f(d1)) << 32) |
                                     (unsigned)(kBase + wc * 64 + k0 + 1));
                }
                s += __shfl_xor_sync(0xffffffffu, s, 1);
                s += __shfl_xor_sync(0xffffffffu, s, 2);
                #pragma unroll
                for (int o = 1; o <= 2; o <<= 1) {
                    unsigned long long o1 = __shfl_xor_sync(0xffffffffu, b1, o);
                    unsigned long long o2 = __shfl_xor_sync(0xffffffffu, b2, o);
                    m2merge(b1, b2, o1, o2);
                }
                if (qcol == 0) {
                    ssum[wc * 128 + rl] = s;
                    smin[(wc * 128 + rl) * 2 + 0] = b1;
                    smin[(wc * 128 + rl) * 2 + 1] = b2;
                }
            }
        }
        __syncthreads();
        if (tid < 128) {
            float s = 0.0f;
            unsigned long long b1 = 0xFFFFFFFFFFFFFFFFull, b2 = 0xFFFFFFFFFFFFFFFFull;
            #pragma unroll
            for (int w = 0; w < 4; w++) {
                s += ssum[w * 128 + tid];
                m2merge(b1, b2, smin[(w * 128 + tid) * 2 + 0], smin[(w * 128 + tid) * 2 + 1]);
            }
            atomicAdd(&g_rowsum[nBase + tid], s);
            size_t cb = (size_t)(nBase + tid) * 32 + (kBase >> 8) * 2;
            g_cand[cb + 0] = b1;
            g_cand[cb + 1] = b2;
        }
        __syncthreads();
        // reset acc for next tile
        #pragma unroll
        for (int mt = 0; mt < 2; mt++)
            #pragma unroll
            for (int nt = 0; nt < 8; nt++)
                #pragma unroll
                for (int e = 0; e < 4; e++) acc[mt][nt][e] = 0.0f;
    }
}

// --------------------------------------------------------------------------
// one warp per row: global min2 over 32 candidates; on near-tie, recompute
// candidate distances with a SEQUENTIAL fp32 fmaf chain over d ascending.
__global__ void finalize_kernel(float* __restrict__ out) {
    __shared__ float blockLoss;
    __shared__ int candList[8][32];
    __shared__ int candCnt[8];
    int lane = threadIdx.x & 31;
    int wid = threadIdx.x >> 5;
    if (threadIdx.x == 0) blockLoss = 0.0f;
    if (lane == 0) candCnt[wid] = 0;
    __syncthreads();
    int n = blockIdx.x * 8 + wid;

    const unsigned long long* cand = &g_cand[(size_t)n * 32];
    unsigned long long b1 = cand[lane];                 // one entry per lane
    unsigned long long b2 = 0xFFFFFFFFFFFFFFFFull;
    #pragma unroll
    for (int o = 16; o; o >>= 1) {
        unsigned long long o1 = __shfl_xor_sync(0xffffffffu, b1, o);
        unsigned long long o2 = __shfl_xor_sync(0xffffffffu, b2, o);
        m2merge(b1, b2, o1, o2);
    }
    float d1 = dec_f((unsigned)(b1 >> 32));
    float d2 = dec_f((unsigned)(b2 >> 32));
    int idx = (int)(unsigned)(b1 & 0xFFFFFFFFull);
    float dmin = d1;

    if (d2 - d1 < EPS_TIE) {
        unsigned long long e0 = cand[lane];
        float de0 = dec_f((unsigned)(e0 >> 32));
        if (de0 - d1 < EPS_TIE) {
            int p = atomicAdd(&candCnt[wid], 1);
            if (p < 32) candList[wid][p] = (int)(unsigned)(e0 & 0xFFFFFFFFull);
        }
        __syncwarp();
        int cnt = candCnt[wid];
        cnt = cnt > 32 ? 32 : cnt;
        unsigned long long mine = 0xFFFFFFFFFFFFFFFFull;
        if (lane < cnt) {
            int k = candList[wid][lane];
            const float* xr = &g_xn[(size_t)n * D_DIM];
            const float* wr = &g_wn[(size_t)k * D_DIM];
            float s = 0.0f;
            #pragma unroll 8
            for (int d = 0; d < D_DIM; d++)
                s = fmaf(xr[d], wr[d], s);
            float dist = 2.0f - 2.0f * s;
            mine = (((unsigned long long)enc_f(dist)) << 32) | (unsigned)k;
        }
        #pragma unroll
        for (int o = 16; o; o >>= 1) {
            unsigned long long v = __shfl_xor_sync(0xffffffffu, mine, o);
            mine = v < mine ? v : mine;
        }
        idx = (int)(unsigned)(mine & 0xFFFFFFFFull);
        dmin = dec_f((unsigned)(mine >> 32));
    }

    if (lane == 0) {
        out[OFF_IDX + n] = (float)idx;
        atomicAdd(&g_counts[idx], 1.0f);
        g_rowsum[n] = 1.0f / g_rowsum[n];
        atomicAdd(&blockLoss, dmin);
    }
    const float* src = &g_wn[(size_t)idx * D_DIM];
    float* dst = &out[OFF_QST + (size_t)n * D_DIM];
    #pragma unroll
    for (int u = 0; u < 8; u++) dst[lane + u * 32] = src[lane + u * 32];
    __syncthreads();
    if (threadIdx.x == 0) atomicAdd(&g_loss, blockLoss);
}

// --------------------------------------------------------------------------
__global__ void scale_kernel(float* __restrict__ out) {
    float* probs = out + OFF_PROBS;
    const size_t total = (size_t)N_ROWS * K_CODES;
    size_t gtid = (size_t)blockIdx.x * blockDim.x + threadIdx.x;
    if (gtid < 3) probs[gtid] *= g_rowsum[0];
    if (gtid == 3) probs[total - 1] *= g_rowsum[N_ROWS - 1];

    float4* p4 = reinterpret_cast<float4*>(probs + 3);
    const size_t total4 = (total - 3) / 4;
    const size_t stride = (size_t)gridDim.x * blockDim.x;
    for (size_t i = gtid; i < total4; i += stride) {
        size_t base = 3 + i * 4;
        float i0 = g_rowsum[(base + 0) >> 12];
        float i1 = g_rowsum[(base + 1) >> 12];
        float i2 = g_rowsum[(base + 2) >> 12];
        float i3 = g_rowsum[(base + 3) >> 12];
        float4 v = p4[i];
        v.x *= i0; v.y *= i1; v.z *= i2; v.w *= i3;
        p4[i] = v;
    }
}

// --------------------------------------------------------------------------
__global__ void scalars_kernel(float* __restrict__ out) {
    __shared__ float sEnt[256];
    __shared__ int sAct[256];
    int tid = threadIdx.x;
    float ent = 0.0f;
    int act = 0;
    for (int k = tid; k < K_CODES; k += 256) {
        float c = g_counts[k];
        float p = c * (1.0f / (float)N_ROWS);
        ent += p * logf(p + 1e-10f);
        act += (c > 0.0f) ? 1 : 0;
    }
    sEnt[tid] = ent;
    sAct[tid] = act;
    __syncthreads();
    for (int s = 128; s; s >>= 1) {
        if (tid < s) { sEnt[tid] += sEnt[tid + s]; sAct[tid] += sAct[tid + s]; }
        __syncthreads();
    }
    if (tid == 0) {
        out[OFF_LOSS] = 0.25f * g_loss / (float)((size_t)N_ROWS * D_DIM);
        out[OFF_PERP] = expf(-sEnt[0]);
        out[OFF_ACT]  = (float)sAct[0];
        out[OFF_USE]  = (float)sAct[0] * (100.0f / (float)K_CODES);
    }
}

// --------------------------------------------------------------------------
extern "C" void kernel_launch(void* const* d_in, const int* in_sizes, int n_in,
                              void* d_out, int out_size) {
    const float* inp = (const float*)d_in[0];   // (16,2048,256) fp32
    const float* w   = (const float*)d_in[1];   // (4096,256) fp32
    float* out = (float*)d_out;

    int dev = 0, sms = 148;
    cudaGetDevice(&dev);
    cudaDeviceGetAttribute(&sms, cudaDevAttrMultiProcessorCount, dev);
    if (sms <= 0 || sms > NTILES) sms = 148;

    cudaFuncSetAttribute(gemm_kernel, cudaFuncAttributeMaxDynamicSharedMemorySize, GEMM_SMEM);

    init_kernel<<<128, 256>>>();
    normsplit_kernel<<<K_CODES / 8, 256>>>(w, K_CODES, 0);
    normsplit_kernel<<<N_ROWS / 8, 256>>>(inp, N_ROWS, 1);
    gemm_kernel<<<sms, 512, GEMM_SMEM>>>(out);
    finalize_kernel<<<N_ROWS / 8, 256>>>(out);
    scale_kernel<<<4096, 256>>>(out);
    scalars_kernel<<<1, 256>>>(out);
}

// round 15
// speedup vs baseline: 1.2069x; 1.0164x over previous
#include <cuda_runtime.h>
#include <cuda_bf16.h>
#include <math.h>
#include <stdint.h>

#define N_ROWS 32768
#define D_DIM  256
#define K_CODES 4096
#define NTILES 4096          // 256 n-tiles x 16 k-tiles
#define EPS_TIE 5e-4f

// ---- output layout (floats) ----
#define OFF_LOSS  0ull
#define OFF_QST   1ull
#define OFF_PROBS (1ull + (unsigned long long)N_ROWS * D_DIM)
#define OFF_PERP  (OFF_PROBS + (unsigned long long)N_ROWS * K_CODES)
#define OFF_IDX   (OFF_PERP + 1ull)
#define OFF_ACT   (OFF_IDX + N_ROWS)
#define OFF_USE   (OFF_ACT + 1ull)

// ---- scratch (static __device__: allocation-free) ----
static __device__ __align__(16) float g_wn[K_CODES * D_DIM];  // normalized fp32
static __device__ __align__(16) float g_xn[N_ROWS * D_DIM];   // normalized fp32
static __device__ float g_rowsum[N_ROWS];
static __device__ unsigned long long g_cand[(size_t)N_ROWS * 32]; // per (row, kTile) min2
static __device__ float g_counts[K_CODES];
static __device__ float g_loss;

// --------------------------------------------------------------------------
__device__ __forceinline__ uint32_t smem_u32(const void* p) {
    uint32_t a;
    asm("{ .reg .u64 t; cvta.to.shared.u64 t, %1; cvt.u32.u64 %0, t; }" : "=r"(a) : "l"(p));
    return a;
}
#define CP_ASYNC16(dst, src) \
    asm volatile("cp.async.cg.shared.global [%0], [%1], 16;" :: "r"(dst), "l"(src))
#define CP_COMMIT() asm volatile("cp.async.commit_group;" ::: "memory")
#define CP_WAIT2()  asm volatile("cp.async.wait_group 2;" ::: "memory")

__device__ __forceinline__ void ldsm_x4(uint32_t* r, uint32_t addr) {
    asm volatile("ldmatrix.sync.aligned.m8n8.x4.shared.b16 {%0,%1,%2,%3}, [%4];"
                 : "=r"(r[0]), "=r"(r[1]), "=r"(r[2]), "=r"(r[3]) : "r"(addr));
}
// tf32 MMA m16n8k8, fp32 accum (baseline sm_80 PTX). Inputs are fp32 bit
// patterns; tensor core uses tf32 precision (low mantissa bits ignored).
__device__ __forceinline__ void mma1688(float* d, const uint32_t* a, const uint32_t* b) {
    asm volatile("mma.sync.aligned.m16n8k8.row.col.f32.tf32.tf32.f32 "
                 "{%0,%1,%2,%3},{%4,%5,%6,%7},{%8,%9},{%0,%1,%2,%3};"
                 : "+f"(d[0]), "+f"(d[1]), "+f"(d[2]), "+f"(d[3])
                 : "r"(a[0]), "r"(a[1]), "r"(a[2]), "r"(a[3]), "r"(b[0]), "r"(b[1]));
}
// 2^t via FFMA-only poly (no MUFU). |rel err| < 2e-5.
__device__ __forceinline__ float fast_exp2(float t) {
    float fi = floorf(t);
    float f = t - fi;
    float p = 1.5403530e-4f;
    p = fmaf(p, f, 1.3333558e-3f);
    p = fmaf(p, f, 9.6181291e-3f);
    p = fmaf(p, f, 5.5504109e-2f);
    p = fmaf(p, f, 2.4022651e-1f);
    p = fmaf(p, f, 6.9314718e-1f);
    p = fmaf(p, f, 1.0f);
    return __int_as_float(__float_as_int(p) + (((int)fi) << 23));
}
__device__ __forceinline__ unsigned enc_f(float x) {
    unsigned u = __float_as_uint(x);
    return (u & 0x80000000u) ? ~u : (u | 0x80000000u);
}
__device__ __forceinline__ float dec_f(unsigned e) {
    return (e & 0x80000000u) ? __uint_as_float(e & 0x7FFFFFFFu) : __uint_as_float(~e);
}
__device__ __forceinline__ void m2merge(unsigned long long& a1, unsigned long long& a2,
                                        unsigned long long b1, unsigned long long b2) {
    unsigned long long lo = a1 < b1 ? a1 : b1;
    unsigned long long hi = a1 < b1 ? b1 : a1;
    unsigned long long mn2 = a2 < b2 ? a2 : b2;
    a1 = lo;
    a2 = hi < mn2 ? hi : mn2;
}
__device__ __forceinline__ void m2insert(unsigned long long& a1, unsigned long long& a2,
                                         unsigned long long v) {
    if (v < a1) { a2 = a1; a1 = v; }
    else if (v < a2) { a2 = v; }
}

// --------------------------------------------------------------------------
__global__ void init_kernel() {
    int i = blockIdx.x * blockDim.x + threadIdx.x;
    if (i < N_ROWS) g_rowsum[i] = 0.0f;
    if (i < K_CODES) g_counts[i] = 0.0f;
    if (i == 0) g_loss = 0.0f;
}

// --------------------------------------------------------------------------
// one warp per row: l2-normalize, store normalized fp32
__global__ void normsplit_kernel(const float* __restrict__ src, int rows, int which) {
    int warp = (blockIdx.x * blockDim.x + threadIdx.x) >> 5;
    int lane = threadIdx.x & 31;
    if (warp >= rows) return;
    const float4* s4 = reinterpret_cast<const float4*>(src + (size_t)warp * D_DIM);
    float4 a = s4[lane];
    float4 b = s4[lane + 32];
    float ss = a.x*a.x + a.y*a.y + a.z*a.z + a.w*a.w
             + b.x*b.x + b.y*b.y + b.z*b.z + b.w*b.w;
    #pragma unroll
    for (int o = 16; o; o >>= 1) ss += __shfl_xor_sync(0xffffffffu, ss, o);
    float sc = 1.0f / fmaxf(sqrtf(ss), 1e-12f);
    a.x *= sc; a.y *= sc; a.z *= sc; a.w *= sc;
    b.x *= sc; b.y *= sc; b.z *= sc; b.w *= sc;
    float4* d4 = reinterpret_cast<float4*>((which ? g_xn : g_wn) + (size_t)warp * D_DIM);
    d4[lane] = a;
    d4[lane + 32] = b;
}

// --------------------------------------------------------------------------
// Persistent tf32 mma.sync GEMM, BK=32, 4-stage ring, ONE syncthreads/chunk.
// CTA tile 128(n) x 256(k); 512 threads, 16 warps (4 wr x 4 wc), warp 32x64.
// smem tile: 128B/row (8 x 16B slots), slot s stored at s ^ (row & 7).
// Producer addressing fully hoisted: dst offsets constant per thread,
// src pointers advance by 32 floats per chunk.
#define STAGE_SZ  49152          // A 16KB (128 rows x 128B) + B 32KB (256 rows)
#define TILE_Aofs 0
#define TILE_Bofs 16384
#define RED_OFF   (4 * STAGE_SZ)
#define GEMM_SMEM (4 * STAGE_SZ + 10240 + 1024)
#define TWO_LOG2E 2.8853900817779268f

struct FragT {
    uint32_t a[2][4];
    uint32_t b[4][4];
};

__device__ __forceinline__ void load_frags_t(FragT& f, uint32_t st, int ks,
                                             const uint32_t* baseA,
                                             const uint32_t* baseB) {
    const uint32_t kx = (uint32_t)(ks << 5);
    #pragma unroll
    for (int mt = 0; mt < 2; mt++)
        ldsm_x4(f.a[mt], st + (baseA[mt] ^ kx));
    #pragma unroll
    for (int pr = 0; pr < 4; pr++)
        ldsm_x4(f.b[pr], st + (baseB[pr] ^ kx));
}

__device__ __forceinline__ void mma_all_t(float (&acc)[2][8][4], const FragT& f) {
    #pragma unroll
    for (int mt = 0; mt < 2; mt++)
        #pragma unroll
        for (int nt = 0; nt < 8; nt++)
            mma1688(acc[mt][nt], f.a[mt], &f.b[nt >> 1][(nt & 1) * 2]);
}

__global__ __launch_bounds__(512, 1) void gemm_kernel(float* __restrict__ out) {
    extern __shared__ char smraw[];
    uint32_t sb = (smem_u32(smraw) + 1023u) & ~1023u;
    char* smem = smraw + (sb - smem_u32(smraw));

    const int tid = threadIdx.x;
    const int wid = tid >> 5;
    const int lane = tid & 31;
    const int wr = wid >> 2;     // 0..3 -> 32 n-rows each
    const int wc = wid & 3;      // 0..3 -> 64 k-cols each
    const int stride = gridDim.x;

    // ---- consumer fragment base offsets (slot XOR folded in) ----
    uint32_t baseA[2], baseB[4];
    {
        int r16 = lane & 15, hA = lane >> 4;
        #pragma unroll
        for (int mt = 0; mt < 2; mt++) {
            int row = wr * 32 + mt * 16 + r16;
            baseA[mt] = TILE_Aofs + row * 128 + (((hA ^ (row & 7)) & 7) << 4);
        }
        int r8 = lane & 7, hiB = (lane >> 4) * 8, hB = (lane >> 3) & 1;
        #pragma unroll
        for (int pr = 0; pr < 4; pr++) {
            int row = wc * 64 + pr * 16 + r8 + hiB;
            baseB[pr] = TILE_Bofs + row * 128 + (((hB ^ (row & 7)) & 7) << 4);
        }
    }

    // ---- producer constant dst offsets + src pointer state ----
    const int prow = tid >> 3;          // 0..63
    const int pslot = tid & 7;
    uint32_t dstA[2], dstB[4];
    #pragma unroll
    for (int rep = 0; rep < 2; rep++) {
        int row = prow + rep * 64;
        dstA[rep] = TILE_Aofs + row * 128 + ((pslot ^ (row & 7)) << 4);
    }
    #pragma unroll
    for (int rep = 0; rep < 4; rep++) {
        int row = prow + rep * 64;
        dstB[rep] = TILE_Bofs + row * 128 + ((pslot ^ (row & 7)) << 4);
    }

    float acc[2][8][4];
    #pragma unroll
    for (int mt = 0; mt < 2; mt++)
        #pragma unroll
        for (int nt = 0; nt < 8; nt++)
            #pragma unroll
            for (int e = 0; e < 4; e++) acc[mt][nt][e] = 0.0f;

    FragT fr;

    // producer state
    int pt = blockIdx.x, pc = 0;
    const float* srcA = g_xn + (size_t)((pt >> 4) * 128 + prow) * D_DIM + pslot * 4;
    const float* srcB = g_wn + (size_t)((pt & 15) * 256 + prow) * D_DIM + pslot * 4;
    bool pvalid = (pt < NTILES);

    // prologue: 3 chunks into stages 0,1,2 (no tile wrap: 3 < 8)
    #pragma unroll
    for (int s = 0; s < 3; s++) {
        uint32_t st = sb + s * STAGE_SZ;
        if (pvalid) {
            CP_ASYNC16(st + dstA[0], srcA);
            CP_ASYNC16(st + dstA[1], srcA + 64 * D_DIM);
            CP_ASYNC16(st + dstB[0], srcB);
            CP_ASYNC16(st + dstB[1], srcB + 64 * D_DIM);
            CP_ASYNC16(st + dstB[2], srcB + 128 * D_DIM);
            CP_ASYNC16(st + dstB[3], srcB + 192 * D_DIM);
        }
        CP_COMMIT();
        srcA += 32; srcB += 32;
        pc++;
    }

    int gphase = 0;
    float* probs = out + OFF_PROBS;
    const int qrow = lane >> 2;
    const int qcol = lane & 3;
    float* ssum = reinterpret_cast<float*>(smem + RED_OFF);                         // [4][128]
    unsigned long long* smin = reinterpret_cast<unsigned long long*>(smem + RED_OFF + 2048); // [4][128][2]

    for (int t = blockIdx.x; t < NTILES; t += stride) {
        const int nBase = (t >> 4) * 128;
        const int kBase = (t & 15) * 256;

        for (int c = 0; c < 8; c++) {
            uint32_t st = sb + gphase * STAGE_SZ;
            CP_WAIT2();            // this chunk's stage complete (<=2 younger pending)
            __syncthreads();       // also: all warps finished reading stage (gphase+3)%4
            // refill the stage consumed last chunk (safe: barrier above)
            {
                uint32_t pst = sb + ((gphase + 3) & 3) * STAGE_SZ;
                if (pvalid) {
                    CP_ASYNC16(pst + dstA[0], srcA);
                    CP_ASYNC16(pst + dstA[1], srcA + 64 * D_DIM);
                    CP_ASYNC16(pst + dstB[0], srcB);
                    CP_ASYNC16(pst + dstB[1], srcB + 64 * D_DIM);
                    CP_ASYNC16(pst + dstB[2], srcB + 128 * D_DIM);
                    CP_ASYNC16(pst + dstB[3], srcB + 192 * D_DIM);
                }
                CP_COMMIT();
                srcA += 32; srcB += 32;
                if (++pc == 8) {
                    pc = 0; pt += stride;
                    pvalid = (pt < NTILES);
                    if (pvalid) {
                        srcA = g_xn + (size_t)((pt >> 4) * 128 + prow) * D_DIM + pslot * 4;
                        srcB = g_wn + (size_t)((pt & 15) * 256 + prow) * D_DIM + pslot * 4;
                    }
                }
            }
            #pragma unroll
            for (int ks = 0; ks < 4; ks++) {
                load_frags_t(fr, st, ks, baseA, baseB);
                mma_all_t(acc, fr);
            }
            gphase = (gphase + 1) & 3;
        }

        // ---- epilogue: probs, rowsum, per-CTA min2 candidates ----
        #pragma unroll
        for (int mt = 0; mt < 2; mt++) {
            #pragma unroll
            for (int hh = 0; hh < 2; hh++) {
                int rl = wr * 32 + mt * 16 + hh * 8 + qrow;
                size_t rowOff = (size_t)(nBase + rl) * K_CODES + kBase + wc * 64;
                float s = 0.0f;
                unsigned long long b1 = 0xFFFFFFFFFFFFFFFFull, b2 = 0xFFFFFFFFFFFFFFFFull;
                #pragma unroll
                for (int nt = 0; nt < 8; nt++) {
                    float v0 = acc[mt][nt][hh * 2 + 0];
                    float v1 = acc[mt][nt][hh * 2 + 1];
                    int k0 = nt * 8 + qcol * 2;
                    float d0 = fmaf(-2.0f, v0, 2.0f);
                    float d1 = fmaf(-2.0f, v1, 2.0f);
                    float e0 = fast_exp2(v0 * TWO_LOG2E);
                    float e1 = fast_exp2(v1 * TWO_LOG2E);
                    probs[rowOff + k0] = e0;
                    probs[rowOff + k0 + 1] = e1;
                    s += e0 + e1;
                    m2insert(b1, b2, (((unsigned long long)enc_f(d0)) << 32) |
                                     (unsigned)(kBase + wc * 64 + k0));
                    m2insert(b1, b2, (((unsigned long long)enc_f(d1)) << 32) |
                                     (unsigned)(kBase + wc * 64 + k0 + 1));
                }
                s += __shfl_xor_sync(0xffffffffu, s, 1);
                s += __shfl_xor_sync(0xffffffffu, s, 2);
                #pragma unroll
                for (int o = 1; o <= 2; o <<= 1) {
                    unsigned long long o1 = __shfl_xor_sync(0xffffffffu, b1, o);
                    unsigned long long o2 = __shfl_xor_sync(0xffffffffu, b2, o);
                    m2merge(b1, b2, o1, o2);
                }
                if (qcol == 0) {
                    ssum[wc * 128 + rl] = s;
                    smin[(wc * 128 + rl) * 2 + 0] = b1;
                    smin[(wc * 128 + rl) * 2 + 1] = b2;
                }
            }
        }
        __syncthreads();
        if (tid < 128) {
            float s = 0.0f;
            unsigned long long b1 = 0xFFFFFFFFFFFFFFFFull, b2 = 0xFFFFFFFFFFFFFFFFull;
            #pragma unroll
            for (int w = 0; w < 4; w++) {
                s += ssum[w * 128 + tid];
                m2merge(b1, b2, smin[(w * 128 + tid) * 2 + 0], smin[(w * 128 + tid) * 2 + 1]);
            }
            atomicAdd(&g_rowsum[nBase + tid], s);
            size_t cb = (size_t)(nBase + tid) * 32 + (kBase >> 8) * 2;
            g_cand[cb + 0] = b1;
            g_cand[cb + 1] = b2;
        }
        __syncthreads();
        // reset acc for next tile
        #pragma unroll
        for (int mt = 0; mt < 2; mt++)
            #pragma unroll
            for (int nt = 0; nt < 8; nt++)
                #pragma unroll
                for (int e = 0; e < 4; e++) acc[mt][nt][e] = 0.0f;
    }
}

// --------------------------------------------------------------------------
// one warp per row: global min2 over 32 candidates; on near-tie, recompute
// candidate distances with a SEQUENTIAL fp32 fmaf chain over d ascending.
__global__ void finalize_kernel(float* __restrict__ out) {
    __shared__ float blockLoss;
    __shared__ int candList[8][32];
    __shared__ int candCnt[8];
    int lane = threadIdx.x & 31;
    int wid = threadIdx.x >> 5;
    if (threadIdx.x == 0) blockLoss = 0.0f;
    if (lane == 0) candCnt[wid] = 0;
    __syncthreads();
    int n = blockIdx.x * 8 + wid;

    const unsigned long long* cand = &g_cand[(size_t)n * 32];
    unsigned long long b1 = cand[lane];                 // one entry per lane
    unsigned long long b2 = 0xFFFFFFFFFFFFFFFFull;
    #pragma unroll
    for (int o = 16; o; o >>= 1) {
        unsigned long long o1 = __shfl_xor_sync(0xffffffffu, b1, o);
        unsigned long long o2 = __shfl_xor_sync(0xffffffffu, b2, o);
        m2merge(b1, b2, o1, o2);
    }
    float d1 = dec_f((unsigned)(b1 >> 32));
    float d2 = dec_f((unsigned)(b2 >> 32));
    int idx = (int)(unsigned)(b1 & 0xFFFFFFFFull);
    float dmin = d1;

    if (d2 - d1 < EPS_TIE) {
        unsigned long long e0 = cand[lane];
        float de0 = dec_f((unsigned)(e0 >> 32));
        if (de0 - d1 < EPS_TIE) {
            int p = atomicAdd(&candCnt[wid], 1);
            if (p < 32) candList[wid][p] = (int)(unsigned)(e0 & 0xFFFFFFFFull);
        }
        __syncwarp();
        int cnt = candCnt[wid];
        cnt = cnt > 32 ? 32 : cnt;
        unsigned long long mine = 0xFFFFFFFFFFFFFFFFull;
        if (lane < cnt) {
            int k = candList[wid][lane];
            const float* xr = &g_xn[(size_t)n * D_DIM];
            const float* wr = &g_wn[(size_t)k * D_DIM];
            float s = 0.0f;
            #pragma unroll 8
            for (int d = 0; d < D_DIM; d++)
                s = fmaf(xr[d], wr[d], s);
            float dist = 2.0f - 2.0f * s;
            mine = (((unsigned long long)enc_f(dist)) << 32) | (unsigned)k;
        }
        #pragma unroll
        for (int o = 16; o; o >>= 1) {
            unsigned long long v = __shfl_xor_sync(0xffffffffu, mine, o);
            mine = v < mine ? v : mine;
        }
        idx = (int)(unsigned)(mine & 0xFFFFFFFFull);
        dmin = dec_f((unsigned)(mine >> 32));
    }

    if (lane == 0) {
        out[OFF_IDX + n] = (float)idx;
        atomicAdd(&g_counts[idx], 1.0f);
        g_rowsum[n] = 1.0f / g_rowsum[n];
        atomicAdd(&blockLoss, dmin);
    }
    const float* src = &g_wn[(size_t)idx * D_DIM];
    float* dst = &out[OFF_QST + (size_t)n * D_DIM];
    #pragma unroll
    for (int u = 0; u < 8; u++) dst[lane + u * 32] = src[lane + u * 32];
    __syncthreads();
    if (threadIdx.x == 0) atomicAdd(&g_loss, blockLoss);
}

// --------------------------------------------------------------------------
__global__ void scale_kernel(float* __restrict__ out) {
    float* probs = out + OFF_PROBS;
    const size_t total = (size_t)N_ROWS * K_CODES;
    size_t gtid = (size_t)blockIdx.x * blockDim.x + threadIdx.x;
    if (gtid < 3) probs[gtid] *= g_rowsum[0];
    if (gtid == 3) probs[total - 1] *= g_rowsum[N_ROWS - 1];

    float4* p4 = reinterpret_cast<float4*>(probs + 3);
    const size_t total4 = (total - 3) / 4;
    const size_t stride = (size_t)gridDim.x * blockDim.x;
    for (size_t i = gtid; i < total4; i += stride) {
        size_t base = 3 + i * 4;
        float i0 = g_rowsum[(base + 0) >> 12];
        float i1 = g_rowsum[(base + 1) >> 12];
        float i2 = g_rowsum[(base + 2) >> 12];
        float i3 = g_rowsum[(base + 3) >> 12];
        float4 v = p4[i];
        v.x *= i0; v.y *= i1; v.z *= i2; v.w *= i3;
        p4[i] = v;
    }
}

// --------------------------------------------------------------------------
__global__ void scalars_kernel(float* __restrict__ out) {
    __shared__ float sEnt[256];
    __shared__ int sAct[256];
    int tid = threadIdx.x;
    float ent = 0.0f;
    int act = 0;
    for (int k = tid; k < K_CODES; k += 256) {
        float c = g_counts[k];
        float p = c * (1.0f / (float)N_ROWS);
        ent += p * logf(p + 1e-10f);
        act += (c > 0.0f) ? 1 : 0;
    }
    sEnt[tid] = ent;
    sAct[tid] = act;
    __syncthreads();
    for (int s = 128; s; s >>= 1) {
        if (tid < s) { sEnt[tid] += sEnt[tid + s]; sAct[tid] += sAct[tid + s]; }
        __syncthreads();
    }
    if (tid == 0) {
        out[OFF_LOSS] = 0.25f * g_loss / (float)((size_t)N_ROWS * D_DIM);
        out[OFF_PERP] = expf(-sEnt[0]);
        out[OFF_ACT]  = (float)sAct[0];
        out[OFF_USE]  = (float)sAct[0] * (100.0f / (float)K_CODES);
    }
}

// --------------------------------------------------------------------------
extern "C" void kernel_launch(void* const* d_in, const int* in_sizes, int n_in,
                              void* d_out, int out_size) {
    const float* inp = (const float*)d_in[0];   // (16,2048,256) fp32
    const float* w   = (const float*)d_in[1];   // (4096,256) fp32
    float* out = (float*)d_out;

    int dev = 0, sms = 148;
    cudaGetDevice(&dev);
    cudaDeviceGetAttribute(&sms, cudaDevAttrMultiProcessorCount, dev);
    if (sms <= 0 || sms > NTILES) sms = 148;

    cudaFuncSetAttribute(gemm_kernel, cudaFuncAttributeMaxDynamicSharedMemorySize, GEMM_SMEM);

    init_kernel<<<128, 256>>>();
    normsplit_kernel<<<K_CODES / 8, 256>>>(w, K_CODES, 0);
    normsplit_kernel<<<N_ROWS / 8, 256>>>(inp, N_ROWS, 1);
    gemm_kernel<<<sms, 512, GEMM_SMEM>>>(out);
    finalize_kernel<<<N_ROWS / 8, 256>>>(out);
    scale_kernel<<<4096, 256>>>(out);
    scalars_kernel<<<1, 256>>>(out);
}